// round 4
// baseline (speedup 1.0000x reference)
#include <cuda_runtime.h>
#include <cuda_bf16.h>
#include <cstdint>
#include <math.h>

#define NBATCH  512
#define T       1042
#define TP      1056
#define TPQ     (TP/4)
#define KE      6400
#define KT      544
#define M_EMB   8192
#define M_PAIR  65536
#define M_REL   4096

// ---------------- scratch (device globals; no allocation) ----------------
__device__ float g_tagged[(size_t)M_EMB * KT];
__device__ float g_P[(size_t)M_EMB * TP];
__device__ float g_Q[(size_t)M_EMB * TP];
__device__ float g_H2[(size_t)M_PAIR * TP];
__device__ float g_R[(size_t)M_EMB * TP];
__device__ float g_rel[(size_t)M_REL * TP];
__device__ float g_Hf[(size_t)M_REL * TP];
__device__ float g_fo[M_REL];
__device__ float g_WembT[(size_t)512 * KE];
__device__ float g_W1tT[(size_t)TP * KT];
__device__ float g_W1bT[(size_t)TP * KT];
__device__ float g_W2T[(size_t)TP * TP];
__device__ float g_W3T[(size_t)TP * TP];
__device__ float g_Wf1T[(size_t)TP * TP];
__device__ float g_Wf2p[TP];
__device__ float g_b1[TP];
__device__ float g_b2[TP];
__device__ float g_b3[TP];
__device__ float g_bf1[TP];

// ---------------- helpers -------------------------------------------------
// Split v into hi = bf16(v), lo = bf16(v - hi); return raw 16-bit patterns.
__device__ __forceinline__ void split_bf16(float v, uint32_t& h, uint32_t& l) {
    __nv_bfloat16 hb = __float2bfloat16(v);
    float hf = __bfloat162float(hb);
    __nv_bfloat16 lb = __float2bfloat16(v - hf);
    h = (uint32_t)__bfloat16_as_ushort(hb);
    l = (uint32_t)__bfloat16_as_ushort(lb);
}

__device__ __forceinline__ void mma16(float acc[4], const uint32_t a[4], const uint32_t b[2]) {
    asm volatile(
        "mma.sync.aligned.m16n8k16.row.col.f32.bf16.bf16.f32 "
        "{%0,%1,%2,%3},{%4,%5,%6,%7},{%8,%9},{%0,%1,%2,%3};"
        : "+f"(acc[0]), "+f"(acc[1]), "+f"(acc[2]), "+f"(acc[3])
        : "r"(a[0]), "r"(a[1]), "r"(a[2]), "r"(a[3]), "r"(b[0]), "r"(b[1]));
}

// ================= 3x-BF16 mma.sync GEMM ==================================
// C[M x N] = A[M x K] @ Bt[N x K]^T.  BM=BN=128, BK=16, 256 threads.
// Warp grid 2(m) x 4(n); warp tile 64x32; frags m16n8k16 (bf16, fp32 acc).
// Split: A=Ah+Al, B=Bh+Bl (bf16 each); acc += Ah*Bh + Ah*Bl + Al*Bh.
// EPI: 0 none, 1 +bias, 2 +bias+relu, 3 +bias+relu+sum over groups of 8 rows.
// AFUSE: A row computed as relu(A[p-row] + A2[q-row] + Ab) on the fly.
//
// Smem per stage (u32 units), fragment-permuted so consumers use plain v4/v2:
//   A: [fragblk 0..7][lane][reg0..3]   (128 u32 per 16-row block)
//   B: [fragblk 0..15][lane][reg0..1]  (64 u32 per 8-col block)
template<int EPI, int AFUSE>
__global__ void __launch_bounds__(256, 1) mmagemm_k(
    const float* __restrict__ A, int lda,
    const float* __restrict__ A2, const float* __restrict__ Ab,
    const float* __restrict__ B, int ldb, int Ncols,
    float* __restrict__ C, int ldc,
    int K, const float* __restrict__ bias)
{
    extern __shared__ uint32_t smu[];
    constexpr int A_HI = 0;
    constexpr int A_LO = 1032;          // 1024 + 8 pad
    constexpr int B_HI = 2064;
    constexpr int B_LO = 3096;
    constexpr int STG  = 4128;          // u32 per stage (16.5 KB)

    const int t  = threadIdx.x;
    const int m0 = blockIdx.y * 128, n0 = blockIdx.x * 128;

    // ---- producer addressing ----
    const int prow = t >> 1, pks = t & 1;           // row 0..127, k-half 0/1
    const int p8 = prow & 7, rb8 = (prow >> 3) & 1;
    const int fb = prow >> 4, nb = prow >> 3;
    const float *ApA, *ApQ = nullptr;
    if (AFUSE) {
        int gr = m0 + prow;
        int bb = gr >> 7, kk = (gr >> 3) & 15, jj = gr & 7;
        ApA = A  + (size_t)(bb * 16 + jj) * lda + pks * 8;
        ApQ = A2 + (size_t)(bb * 16 + kk) * lda + pks * 8;
    } else {
        ApA = A + (size_t)(m0 + prow) * lda + pks * 8;
    }
    const float* Bpp = B + (size_t)(n0 + prow) * ldb + pks * 8;
    const bool bval = (n0 + prow) < Ncols;

    float va[8], vb[8];

    // ---- consumer addressing ----
    const int L = t & 31, wid = t >> 5, wm = wid >> 2, wn = wid & 3;
    float acc[4][4][4];
    #pragma unroll
    for (int i = 0; i < 4; i++)
        #pragma unroll
        for (int j = 0; j < 4; j++)
            #pragma unroll
            for (int v = 0; v < 4; v++) acc[i][j][v] = 0.f;

    const int KB = K >> 4;

    // ---------- load tile (registers) ----------
    auto ldtile = [&](int k0) {
        if (AFUSE) {
            float4 p0 = *(const float4*)(ApA + k0);
            float4 p1 = *(const float4*)(ApA + k0 + 4);
            float4 q0 = *(const float4*)(ApQ + k0);
            float4 q1 = *(const float4*)(ApQ + k0 + 4);
            float4 c0 = *(const float4*)(Ab + k0 + pks * 8);
            float4 c1 = *(const float4*)(Ab + k0 + pks * 8 + 4);
            va[0] = fmaxf(p0.x + q0.x + c0.x, 0.f);
            va[1] = fmaxf(p0.y + q0.y + c0.y, 0.f);
            va[2] = fmaxf(p0.z + q0.z + c0.z, 0.f);
            va[3] = fmaxf(p0.w + q0.w + c0.w, 0.f);
            va[4] = fmaxf(p1.x + q1.x + c1.x, 0.f);
            va[5] = fmaxf(p1.y + q1.y + c1.y, 0.f);
            va[6] = fmaxf(p1.z + q1.z + c1.z, 0.f);
            va[7] = fmaxf(p1.w + q1.w + c1.w, 0.f);
        } else {
            float4 x0 = *(const float4*)(ApA + k0);
            float4 x1 = *(const float4*)(ApA + k0 + 4);
            va[0] = x0.x; va[1] = x0.y; va[2] = x0.z; va[3] = x0.w;
            va[4] = x1.x; va[5] = x1.y; va[6] = x1.z; va[7] = x1.w;
        }
        float4 y0 = make_float4(0.f, 0.f, 0.f, 0.f);
        float4 y1 = make_float4(0.f, 0.f, 0.f, 0.f);
        if (bval) {
            y0 = *(const float4*)(Bpp + k0);
            y1 = *(const float4*)(Bpp + k0 + 4);
        }
        vb[0] = y0.x; vb[1] = y0.y; vb[2] = y0.z; vb[3] = y0.w;
        vb[4] = y1.x; vb[5] = y1.y; vb[6] = y1.z; vb[7] = y1.w;
    };

    // ---------- split + store tile to smem (fragment-permuted) ----------
    // A elem (row r, k): lane=(r%8)*4+(k%8)/2, reg=(r/8)+2*(k/8), half=k%2.
    // B elem (col n, k): lane=(n%8)*4+(k%8)/2, reg=k/8,           half=k%2.
    auto sttile = [&](uint32_t* stg) {
        #pragma unroll
        for (int j = 0; j < 4; j++) {
            uint32_t h0, l0, h1, l1;
            split_bf16(va[2 * j],     h0, l0);
            split_bf16(va[2 * j + 1], h1, l1);
            int ai = fb * 128 + (p8 * 4 + j) * 4 + rb8 + 2 * pks;
            stg[A_HI + ai] = h0 | (h1 << 16);
            stg[A_LO + ai] = l0 | (l1 << 16);
            uint32_t bh0, bl0, bh1, bl1;
            split_bf16(vb[2 * j],     bh0, bl0);
            split_bf16(vb[2 * j + 1], bh1, bl1);
            int bi = nb * 64 + (p8 * 4 + j) * 2 + pks;
            stg[B_HI + bi] = bh0 | (bh1 << 16);
            stg[B_LO + bi] = bl0 | (bl1 << 16);
        }
    };

    // ---------- consume one stage: 48 MMAs ----------
    auto consume = [&](const uint32_t* stg) {
        uint32_t ah[4][4], al[4][4], bh[4][2], bl[4][2];
        #pragma unroll
        for (int mf = 0; mf < 4; mf++) {
            const uint32_t* ab = stg + (wm * 4 + mf) * 128 + L * 4;
            *(uint4*)ah[mf] = *(const uint4*)(ab + A_HI);
            *(uint4*)al[mf] = *(const uint4*)(ab + A_LO);
        }
        #pragma unroll
        for (int nf = 0; nf < 4; nf++) {
            const uint32_t* bb = stg + (wn * 4 + nf) * 64 + L * 2;
            *(uint2*)bh[nf] = *(const uint2*)(bb + B_HI);
            *(uint2*)bl[nf] = *(const uint2*)(bb + B_LO);
        }
        #pragma unroll
        for (int mf = 0; mf < 4; mf++)
            #pragma unroll
            for (int nf = 0; nf < 4; nf++) {
                mma16(acc[mf][nf], ah[mf], bh[nf]);
                mma16(acc[mf][nf], ah[mf], bl[nf]);
                mma16(acc[mf][nf], al[mf], bh[nf]);
            }
    };

    // ---------- pipelined main loop ----------
    ldtile(0);
    sttile(smu);
    __syncthreads();
    for (int kb = 0; kb < KB; kb++) {
        if (kb + 1 < KB) ldtile((kb + 1) * 16);
        consume(smu + (kb & 1) * STG);
        if (kb + 1 < KB) sttile(smu + ((kb + 1) & 1) * STG);
        __syncthreads();
    }

    // ---------- epilogue ----------
    const int baseRow = m0 + wm * 64;
    const int colBase = n0 + wn * 32 + (L & 3) * 2;
    #pragma unroll
    for (int mf = 0; mf < 4; mf++) {
        #pragma unroll
        for (int nf = 0; nf < 4; nf++) {
            int col = colBase + nf * 8;
            bool cv = col < Ncols;
            float c0 = acc[mf][nf][0], c1 = acc[mf][nf][1];
            float c2 = acc[mf][nf][2], c3 = acc[mf][nf][3];
            if (EPI >= 1) {
                float2 b2 = cv ? *(const float2*)(bias + col) : make_float2(0.f, 0.f);
                c0 += b2.x; c1 += b2.y; c2 += b2.x; c3 += b2.y;
            }
            if (EPI >= 2) {
                c0 = fmaxf(c0, 0.f); c1 = fmaxf(c1, 0.f);
                c2 = fmaxf(c2, 0.f); c3 = fmaxf(c3, 0.f);
            }
            if (EPI == 3) {
                c0 += __shfl_down_sync(0xffffffffu, c0, 16);
                c0 += __shfl_down_sync(0xffffffffu, c0, 8);
                c0 += __shfl_down_sync(0xffffffffu, c0, 4);
                c1 += __shfl_down_sync(0xffffffffu, c1, 16);
                c1 += __shfl_down_sync(0xffffffffu, c1, 8);
                c1 += __shfl_down_sync(0xffffffffu, c1, 4);
                c2 += __shfl_down_sync(0xffffffffu, c2, 16);
                c2 += __shfl_down_sync(0xffffffffu, c2, 8);
                c2 += __shfl_down_sync(0xffffffffu, c2, 4);
                c3 += __shfl_down_sync(0xffffffffu, c3, 16);
                c3 += __shfl_down_sync(0xffffffffu, c3, 8);
                c3 += __shfl_down_sync(0xffffffffu, c3, 4);
                if (L < 4 && cv) {
                    int g = (baseRow + mf * 16) >> 3;
                    *(float2*)(C + (size_t)g * ldc + col)       = make_float2(c0, c1);
                    *(float2*)(C + (size_t)(g + 1) * ldc + col) = make_float2(c2, c3);
                }
            } else {
                if (cv) {
                    int row = baseRow + mf * 16 + (L >> 2);
                    *(float2*)(C + (size_t)row * ldc + col)       = make_float2(c0, c1);
                    *(float2*)(C + (size_t)(row + 8) * ldc + col) = make_float2(c2, c3);
                }
            }
        }
    }
}

// ======================= small kernels ====================================
__global__ void pad2d_k(float* __restrict__ dst, const float* __restrict__ src,
                        int dR, int dC, int sR, int sC, int sStride, int sRowOff)
{
    int idx = blockIdx.x * blockDim.x + threadIdx.x;
    if (idx >= dR * dC) return;
    int r = idx / dC, c = idx % dC;
    float v = 0.f;
    if (r < sR && c < sC) v = src[(size_t)(r + sRowOff) * sStride + c];
    dst[idx] = v;
}

// dst[r, c] = src[(c + rowOff) * sStride + r]  (zero-padded), dst is [DR x DC]
__global__ void transposeT_k(float* __restrict__ dst, const float* __restrict__ src,
                             int DR, int DC, int sR, int sC, int sStride, int rowOff)
{
    __shared__ float tbuf[32][33];
    int c0 = blockIdx.x * 32;
    int r0 = blockIdx.y * 32;
    int tx = threadIdx.x, ty = threadIdx.y;
    #pragma unroll
    for (int i = ty; i < 32; i += 8) {
        int srow = c0 + i, scol = r0 + tx;
        tbuf[i][tx] = (srow < sR && scol < sC) ? src[(size_t)(srow + rowOff) * sStride + scol] : 0.f;
    }
    __syncthreads();
    #pragma unroll
    for (int i = ty; i < 32; i += 8) {
        int r = r0 + i, c = c0 + tx;
        if (r < DR && c < DC) dst[(size_t)r * DC + c] = tbuf[tx][i];
    }
}

__global__ void tagfill_k(float* __restrict__ tg)
{
    int idx = blockIdx.x * blockDim.x + threadIdx.x;   // M_EMB * 32
    if (idx >= M_EMB * 32) return;
    int r = idx >> 5, c = idx & 31;
    int p = r & 15;
    int tt = (p < 8) ? p : 8;
    tg[(size_t)r * KT + 512 + c] = (c == tt) ? 1.f : 0.f;
}

__global__ void relations_k(const float* __restrict__ R, float* __restrict__ rel)
{
    int idx = blockIdx.x * blockDim.x + threadIdx.x;   // NBATCH * TPQ
    if (idx >= NBATCH * TPQ) return;
    int c4 = idx % TPQ;
    int b  = idx / TPQ;
    const float4* r = reinterpret_cast<const float4*>(R) + (size_t)(b * 16) * TPQ + c4;
    float4 cs = make_float4(0.f, 0.f, 0.f, 0.f);
    #pragma unroll
    for (int k = 0; k < 8; k++) {
        float4 v = r[(size_t)k * TPQ];
        cs.x += v.x; cs.y += v.y; cs.z += v.z; cs.w += v.w;
    }
    #pragma unroll
    for (int a = 0; a < 8; a++) {
        float4 v = r[(size_t)(8 + a) * TPQ];
        float4 o = make_float4(cs.x + v.x, cs.y + v.y, cs.z + v.z, cs.w + v.w);
        reinterpret_cast<float4*>(rel)[(size_t)(b * 8 + a) * TPQ + c4] = o;
    }
}

__inline__ __device__ float warp_sum(float v)
{
    #pragma unroll
    for (int o = 16; o; o >>= 1) v += __shfl_down_sync(0xffffffffu, v, o);
    return v;
}

__global__ void fout_k(const float* __restrict__ Hf, const float* __restrict__ W,
                       const float* __restrict__ bf2, float* __restrict__ fo)
{
    int row = blockIdx.x;
    const float* h = Hf + (size_t)row * TP;
    float s = 0.f;
    for (int c = threadIdx.x; c < TP; c += 128) s += h[c] * W[c];
    s = warp_sum(s);
    __shared__ float sh[4];
    if ((threadIdx.x & 31) == 0) sh[threadIdx.x >> 5] = s;
    __syncthreads();
    if (threadIdx.x == 0) fo[row] = sh[0] + sh[1] + sh[2] + sh[3] + bf2[0];
}

__global__ void loss_k(const float* __restrict__ fo, const int* __restrict__ labels,
                       float* __restrict__ out)
{
    int b = threadIdx.x;   // 512 threads
    int lab = labels[b];
    float lsum = 0.f;
    float best = -1e30f; int bi = 0;
    #pragma unroll
    for (int a = 0; a < 8; a++) {
        float f = fo[b * 8 + a];
        float l = fmaxf(f, 0.f) - f * ((a == lab) ? 1.f : 0.f) + log1pf(expf(-fabsf(f)));
        lsum += l;
        if (f > best) { best = f; bi = a; }
    }
    float cor = (bi == lab) ? 1.f : 0.f;
    lsum = warp_sum(lsum);
    cor  = warp_sum(cor);
    __shared__ float sl[16], sc[16];
    int wid = threadIdx.x >> 5, lane = threadIdx.x & 31;
    if (lane == 0) { sl[wid] = lsum; sc[wid] = cor; }
    __syncthreads();
    if (wid == 0) {
        float a = (lane < 16) ? sl[lane] : 0.f;
        float c = (lane < 16) ? sc[lane] : 0.f;
        a = warp_sum(a);
        c = warp_sum(c);
        if (lane == 0) {
            out[0] = a / (float)(NBATCH * 8);
            out[1] = c / (float)NBATCH;
        }
    }
}

// ======================= host =============================================
static inline int cdiv(int a, int b) { return (a + b - 1) / b; }

extern "C" void kernel_launch(void* const* d_in, const int* in_sizes, int n_in,
                              void* d_out, int out_size)
{
    const float* x      = (const float*)d_in[0];
    const float* W_emb  = (const float*)d_in[1];
    const float* b_emb  = (const float*)d_in[2];
    const float* Wg1    = (const float*)d_in[3];
    const float* bg1    = (const float*)d_in[4];
    const float* Wg2    = (const float*)d_in[5];
    const float* bg2    = (const float*)d_in[6];
    const float* Wg3    = (const float*)d_in[7];
    const float* bg3    = (const float*)d_in[8];
    const float* Wf1    = (const float*)d_in[9];
    const float* bf1    = (const float*)d_in[10];
    const float* Wf2    = (const float*)d_in[11];
    const float* bf2    = (const float*)d_in[12];
    const int*   labels = (const int*)d_in[13];
    float* out = (float*)d_out;

    float *tagged, *P, *Q, *H2, *R, *rel, *Hf, *fo;
    float *WembT, *W1tT, *W1bT, *W2T, *W3T, *Wf1T, *Wf2p, *b1p, *b2p, *b3p, *bf1p;
    cudaGetSymbolAddress((void**)&tagged, g_tagged);
    cudaGetSymbolAddress((void**)&P, g_P);
    cudaGetSymbolAddress((void**)&Q, g_Q);
    cudaGetSymbolAddress((void**)&H2, g_H2);
    cudaGetSymbolAddress((void**)&R, g_R);
    cudaGetSymbolAddress((void**)&rel, g_rel);
    cudaGetSymbolAddress((void**)&Hf, g_Hf);
    cudaGetSymbolAddress((void**)&fo, g_fo);
    cudaGetSymbolAddress((void**)&WembT, g_WembT);
    cudaGetSymbolAddress((void**)&W1tT, g_W1tT);
    cudaGetSymbolAddress((void**)&W1bT, g_W1bT);
    cudaGetSymbolAddress((void**)&W2T, g_W2T);
    cudaGetSymbolAddress((void**)&W3T, g_W3T);
    cudaGetSymbolAddress((void**)&Wf1T, g_Wf1T);
    cudaGetSymbolAddress((void**)&Wf2p, g_Wf2p);
    cudaGetSymbolAddress((void**)&b1p, g_b1);
    cudaGetSymbolAddress((void**)&b2p, g_b2);
    cudaGetSymbolAddress((void**)&b3p, g_b3);
    cudaGetSymbolAddress((void**)&bf1p, g_bf1);

    const int SMB = 2 * 4128 * 4;   // 33024 bytes dynamic smem
    cudaFuncSetAttribute(mmagemm_k<1,0>, cudaFuncAttributeMaxDynamicSharedMemorySize, SMB);
    cudaFuncSetAttribute(mmagemm_k<0,0>, cudaFuncAttributeMaxDynamicSharedMemorySize, SMB);
    cudaFuncSetAttribute(mmagemm_k<2,1>, cudaFuncAttributeMaxDynamicSharedMemorySize, SMB);
    cudaFuncSetAttribute(mmagemm_k<3,0>, cudaFuncAttributeMaxDynamicSharedMemorySize, SMB);
    cudaFuncSetAttribute(mmagemm_k<2,0>, cudaFuncAttributeMaxDynamicSharedMemorySize, SMB);

    dim3 tb(32, 8);
    // Transposed / padded weights: Bt[n, k] = W[k, n]
    transposeT_k<<<dim3(200, 16), tb>>>(WembT, W_emb, 512, KE, KE, 512, 512, 0);
    transposeT_k<<<dim3(17, 33), tb>>>(W1tT, Wg1, TP, KT, 521, T, T, 0);
    transposeT_k<<<dim3(17, 33), tb>>>(W1bT, Wg1, TP, KT, 521, T, T, 521);
    transposeT_k<<<dim3(33, 33), tb>>>(W2T,  Wg2, TP, TP, T, T, T, 0);
    transposeT_k<<<dim3(33, 33), tb>>>(W3T,  Wg3, TP, TP, T, T, T, 0);
    transposeT_k<<<dim3(33, 33), tb>>>(Wf1T, Wf1, TP, TP, T, T, T, 0);
    pad2d_k<<<cdiv(TP, 256), 256>>>(Wf2p, Wf2, 1, TP, 1, T, T, 0);
    pad2d_k<<<cdiv(TP, 256), 256>>>(b1p, bg1, 1, TP, 1, T, T, 0);
    pad2d_k<<<cdiv(TP, 256), 256>>>(b2p, bg2, 1, TP, 1, T, T, 0);
    pad2d_k<<<cdiv(TP, 256), 256>>>(b3p, bg3, 1, TP, 1, T, T, 0);
    pad2d_k<<<cdiv(TP, 256), 256>>>(bf1p, bf1, 1, TP, 1, T, T, 0);
    tagfill_k<<<cdiv(M_EMB * 32, 256), 256>>>(tagged);

    // emb = x @ W_emb + b_emb -> tagged[:, 0:512]  (ldc = 544)
    mmagemm_k<1,0><<<dim3(4, M_EMB/128), 256, SMB>>>(
        x, KE, nullptr, nullptr, WembT, KE, 512, tagged, KT, KE, b_emb);
    // P = tagged @ Wg1_top ; Q = tagged @ Wg1_bot
    mmagemm_k<0,0><<<dim3(9, M_EMB/128), 256, SMB>>>(
        tagged, KT, nullptr, nullptr, W1tT, KT, TP, P, TP, KT, nullptr);
    mmagemm_k<0,0><<<dim3(9, M_EMB/128), 256, SMB>>>(
        tagged, KT, nullptr, nullptr, W1bT, KT, TP, Q, TP, KT, nullptr);
    // H2 = relu(relu(P[j]+Q[k]+b1) @ Wg2 + b2)  (H1 expand fused into A producer)
    mmagemm_k<2,1><<<dim3(9, M_PAIR/128), 256, SMB>>>(
        P, TP, Q, b1p, W2T, TP, TP, H2, TP, TP, b2p);
    // R[b,k] = sum_j relu(H2 @ Wg3 + b3)  (8-row reduction fused in epilogue)
    mmagemm_k<3,0><<<dim3(9, M_PAIR/128), 256, SMB>>>(
        H2, TP, nullptr, nullptr, W3T, TP, TP, R, TP, TP, b3p);
    // relations
    relations_k<<<cdiv(NBATCH * TPQ, 256), 256>>>(R, rel);
    // Hf = relu(rel @ Wf1 + bf1)
    mmagemm_k<2,0><<<dim3(9, M_REL/128), 256, SMB>>>(
        rel, TP, nullptr, nullptr, Wf1T, TP, TP, Hf, TP, TP, bf1p);
    fout_k<<<M_REL, 128>>>(Hf, Wf2p, bf2, fo);
    loss_k<<<1, 512>>>(fo, labels, out);
}

// round 5
// speedup vs baseline: 1.4160x; 1.4160x over previous
#include <cuda_runtime.h>
#include <cuda_bf16.h>
#include <cstdint>
#include <math.h>

#define NBATCH  512
#define T       1042
#define TP      1056
#define TPQ     (TP/4)
#define KE      6400
#define KT      544
#define M_EMB   8192
#define M_PAIR  65536
#define M_REL   4096

// ---------------- scratch (device globals; no allocation) ----------------
__device__ float g_tagged[(size_t)M_EMB * KT];
__device__ float g_P[(size_t)M_EMB * TP];
__device__ float g_Q[(size_t)M_EMB * TP];
__device__ float g_H2[(size_t)M_PAIR * TP];
__device__ float g_R[(size_t)M_EMB * TP];
__device__ float g_rel[(size_t)M_REL * TP];
__device__ float g_Hf[(size_t)M_REL * TP];
__device__ float g_fo[M_REL];
__device__ float g_WembT[(size_t)512 * KE];
__device__ float g_W1tT[(size_t)TP * KT];
__device__ float g_W1bT[(size_t)TP * KT];
__device__ float g_W2T[(size_t)TP * TP];
__device__ float g_W3T[(size_t)TP * TP];
__device__ float g_Wf1T[(size_t)TP * TP];
__device__ float g_Wf2p[TP];
__device__ float g_b1[TP];
__device__ float g_b2[TP];
__device__ float g_b3[TP];
__device__ float g_bf1[TP];

// ---------------- helpers -------------------------------------------------
// Split v into hi = bf16(v), lo = bf16(v - hi); return raw 16-bit patterns.
__device__ __forceinline__ void split_bf16(float v, uint32_t& h, uint32_t& l) {
    __nv_bfloat16 hb = __float2bfloat16(v);
    float hf = __bfloat162float(hb);
    __nv_bfloat16 lb = __float2bfloat16(v - hf);
    h = (uint32_t)__bfloat16_as_ushort(hb);
    l = (uint32_t)__bfloat16_as_ushort(lb);
}

__device__ __forceinline__ void mma16(float acc[4], const uint32_t a[4], const uint32_t b[2]) {
    asm volatile(
        "mma.sync.aligned.m16n8k16.row.col.f32.bf16.bf16.f32 "
        "{%0,%1,%2,%3},{%4,%5,%6,%7},{%8,%9},{%0,%1,%2,%3};"
        : "+f"(acc[0]), "+f"(acc[1]), "+f"(acc[2]), "+f"(acc[3])
        : "r"(a[0]), "r"(a[1]), "r"(a[2]), "r"(a[3]), "r"(b[0]), "r"(b[1]));
}

// ================= 3x-BF16 mma.sync GEMM ==================================
// C[M x N] = A[M x K] @ Bt[N x K]^T.  BM=BN=128, BK=16, 256 threads.
// Warp grid 2(m) x 4(n); warp tile 64x32; frags m16n8k16 (bf16, fp32 acc).
// Split: A=Ah+Al, B=Bh+Bl (bf16 each); acc += Ah*Bh + Ah*Bl + Al*Bh.
// EPI: 0 none, 1 +bias, 2 +bias+relu, 3 +bias+relu+sum over groups of 8 rows.
// AFUSE: A row computed as relu(A[p-row] + A2[q-row] + Ab) on the fly.
//
// Smem per stage (u32 units), fragment-permuted so consumers use plain v4/v2:
//   A: [fragblk 0..7][lane][reg0..3]   (128 u32 per 16-row block)
//   B: [fragblk 0..15][lane][reg0..1]  (64 u32 per 8-col block)
template<int EPI, int AFUSE>
__global__ void __launch_bounds__(256, 1) mmagemm_k(
    const float* __restrict__ A, int lda,
    const float* __restrict__ A2, const float* __restrict__ Ab,
    const float* __restrict__ B, int ldb, int Ncols,
    float* __restrict__ C, int ldc,
    int K, const float* __restrict__ bias)
{
    extern __shared__ uint32_t smu[];
    constexpr int A_HI = 0;
    constexpr int A_LO = 1032;          // 1024 + 8 pad
    constexpr int B_HI = 2064;
    constexpr int B_LO = 3096;
    constexpr int STG  = 4128;          // u32 per stage (16.5 KB)

    const int t  = threadIdx.x;
    const int m0 = blockIdx.y * 128, n0 = blockIdx.x * 128;

    // ---- producer addressing ----
    const int prow = t >> 1, pks = t & 1;           // row 0..127, k-half 0/1
    const int p8 = prow & 7, rb8 = (prow >> 3) & 1;
    const int fb = prow >> 4, nb = prow >> 3;
    const float *ApA, *ApQ = nullptr;
    if (AFUSE) {
        int gr = m0 + prow;
        int bb = gr >> 7, kk = (gr >> 3) & 15, jj = gr & 7;
        ApA = A  + (size_t)(bb * 16 + jj) * lda + pks * 8;
        ApQ = A2 + (size_t)(bb * 16 + kk) * lda + pks * 8;
    } else {
        ApA = A + (size_t)(m0 + prow) * lda + pks * 8;
    }
    const float* Bpp = B + (size_t)(n0 + prow) * ldb + pks * 8;
    const bool bval = (n0 + prow) < Ncols;

    float va[8], vb[8];

    // ---- consumer addressing ----
    const int L = t & 31, wid = t >> 5, wm = wid >> 2, wn = wid & 3;
    float acc[4][4][4];
    #pragma unroll
    for (int i = 0; i < 4; i++)
        #pragma unroll
        for (int j = 0; j < 4; j++)
            #pragma unroll
            for (int v = 0; v < 4; v++) acc[i][j][v] = 0.f;

    const int KB = K >> 4;

    // ---------- load tile (registers) ----------
    auto ldtile = [&](int k0) {
        if (AFUSE) {
            float4 p0 = *(const float4*)(ApA + k0);
            float4 p1 = *(const float4*)(ApA + k0 + 4);
            float4 q0 = *(const float4*)(ApQ + k0);
            float4 q1 = *(const float4*)(ApQ + k0 + 4);
            float4 c0 = *(const float4*)(Ab + k0 + pks * 8);
            float4 c1 = *(const float4*)(Ab + k0 + pks * 8 + 4);
            va[0] = fmaxf(p0.x + q0.x + c0.x, 0.f);
            va[1] = fmaxf(p0.y + q0.y + c0.y, 0.f);
            va[2] = fmaxf(p0.z + q0.z + c0.z, 0.f);
            va[3] = fmaxf(p0.w + q0.w + c0.w, 0.f);
            va[4] = fmaxf(p1.x + q1.x + c1.x, 0.f);
            va[5] = fmaxf(p1.y + q1.y + c1.y, 0.f);
            va[6] = fmaxf(p1.z + q1.z + c1.z, 0.f);
            va[7] = fmaxf(p1.w + q1.w + c1.w, 0.f);
        } else {
            float4 x0 = *(const float4*)(ApA + k0);
            float4 x1 = *(const float4*)(ApA + k0 + 4);
            va[0] = x0.x; va[1] = x0.y; va[2] = x0.z; va[3] = x0.w;
            va[4] = x1.x; va[5] = x1.y; va[6] = x1.z; va[7] = x1.w;
        }
        float4 y0 = make_float4(0.f, 0.f, 0.f, 0.f);
        float4 y1 = make_float4(0.f, 0.f, 0.f, 0.f);
        if (bval) {
            y0 = *(const float4*)(Bpp + k0);
            y1 = *(const float4*)(Bpp + k0 + 4);
        }
        vb[0] = y0.x; vb[1] = y0.y; vb[2] = y0.z; vb[3] = y0.w;
        vb[4] = y1.x; vb[5] = y1.y; vb[6] = y1.z; vb[7] = y1.w;
    };

    // ---------- split + store tile to smem (fragment-permuted) ----------
    // A elem (row r, k): lane=(r%8)*4+(k%8)/2, reg=(r/8)+2*(k/8), half=k%2.
    // B elem (col n, k): lane=(n%8)*4+(k%8)/2, reg=k/8,           half=k%2.
    auto sttile = [&](uint32_t* stg) {
        #pragma unroll
        for (int j = 0; j < 4; j++) {
            uint32_t h0, l0, h1, l1;
            split_bf16(va[2 * j],     h0, l0);
            split_bf16(va[2 * j + 1], h1, l1);
            int ai = fb * 128 + (p8 * 4 + j) * 4 + rb8 + 2 * pks;
            stg[A_HI + ai] = h0 | (h1 << 16);
            stg[A_LO + ai] = l0 | (l1 << 16);
            uint32_t bh0, bl0, bh1, bl1;
            split_bf16(vb[2 * j],     bh0, bl0);
            split_bf16(vb[2 * j + 1], bh1, bl1);
            int bi = nb * 64 + (p8 * 4 + j) * 2 + pks;
            stg[B_HI + bi] = bh0 | (bh1 << 16);
            stg[B_LO + bi] = bl0 | (bl1 << 16);
        }
    };

    // ---------- consume one stage: 48 MMAs ----------
    auto consume = [&](const uint32_t* stg) {
        uint32_t ah[4][4], al[4][4], bh[4][2], bl[4][2];
        #pragma unroll
        for (int mf = 0; mf < 4; mf++) {
            const uint32_t* ab = stg + (wm * 4 + mf) * 128 + L * 4;
            *(uint4*)ah[mf] = *(const uint4*)(ab + A_HI);
            *(uint4*)al[mf] = *(const uint4*)(ab + A_LO);
        }
        #pragma unroll
        for (int nf = 0; nf < 4; nf++) {
            const uint32_t* bb = stg + (wn * 4 + nf) * 64 + L * 2;
            *(uint2*)bh[nf] = *(const uint2*)(bb + B_HI);
            *(uint2*)bl[nf] = *(const uint2*)(bb + B_LO);
        }
        #pragma unroll
        for (int mf = 0; mf < 4; mf++)
            #pragma unroll
            for (int nf = 0; nf < 4; nf++) {
                mma16(acc[mf][nf], ah[mf], bh[nf]);
                mma16(acc[mf][nf], ah[mf], bl[nf]);
                mma16(acc[mf][nf], al[mf], bh[nf]);
            }
    };

    // ---------- pipelined main loop ----------
    ldtile(0);
    sttile(smu);
    __syncthreads();
    for (int kb = 0; kb < KB; kb++) {
        if (kb + 1 < KB) ldtile((kb + 1) * 16);
        consume(smu + (kb & 1) * STG);
        if (kb + 1 < KB) sttile(smu + ((kb + 1) & 1) * STG);
        __syncthreads();
    }

    // ---------- epilogue ----------
    const int baseRow = m0 + wm * 64;
    const int colBase = n0 + wn * 32 + (L & 3) * 2;
    #pragma unroll
    for (int mf = 0; mf < 4; mf++) {
        #pragma unroll
        for (int nf = 0; nf < 4; nf++) {
            int col = colBase + nf * 8;
            bool cv = col < Ncols;
            float c0 = acc[mf][nf][0], c1 = acc[mf][nf][1];
            float c2 = acc[mf][nf][2], c3 = acc[mf][nf][3];
            if (EPI >= 1) {
                float2 b2 = cv ? *(const float2*)(bias + col) : make_float2(0.f, 0.f);
                c0 += b2.x; c1 += b2.y; c2 += b2.x; c3 += b2.y;
            }
            if (EPI >= 2) {
                c0 = fmaxf(c0, 0.f); c1 = fmaxf(c1, 0.f);
                c2 = fmaxf(c2, 0.f); c3 = fmaxf(c3, 0.f);
            }
            if (EPI == 3) {
                c0 += __shfl_down_sync(0xffffffffu, c0, 16);
                c0 += __shfl_down_sync(0xffffffffu, c0, 8);
                c0 += __shfl_down_sync(0xffffffffu, c0, 4);
                c1 += __shfl_down_sync(0xffffffffu, c1, 16);
                c1 += __shfl_down_sync(0xffffffffu, c1, 8);
                c1 += __shfl_down_sync(0xffffffffu, c1, 4);
                c2 += __shfl_down_sync(0xffffffffu, c2, 16);
                c2 += __shfl_down_sync(0xffffffffu, c2, 8);
                c2 += __shfl_down_sync(0xffffffffu, c2, 4);
                c3 += __shfl_down_sync(0xffffffffu, c3, 16);
                c3 += __shfl_down_sync(0xffffffffu, c3, 8);
                c3 += __shfl_down_sync(0xffffffffu, c3, 4);
                if (L < 4 && cv) {
                    int g = (baseRow + mf * 16) >> 3;
                    *(float2*)(C + (size_t)g * ldc + col)       = make_float2(c0, c1);
                    *(float2*)(C + (size_t)(g + 1) * ldc + col) = make_float2(c2, c3);
                }
            } else {
                if (cv) {
                    int row = baseRow + mf * 16 + (L >> 2);
                    *(float2*)(C + (size_t)row * ldc + col)       = make_float2(c0, c1);
                    *(float2*)(C + (size_t)(row + 8) * ldc + col) = make_float2(c2, c3);
                }
            }
        }
    }
}

// ======================= small kernels ====================================
__global__ void pad2d_k(float* __restrict__ dst, const float* __restrict__ src,
                        int dR, int dC, int sR, int sC, int sStride, int sRowOff)
{
    int idx = blockIdx.x * blockDim.x + threadIdx.x;
    if (idx >= dR * dC) return;
    int r = idx / dC, c = idx % dC;
    float v = 0.f;
    if (r < sR && c < sC) v = src[(size_t)(r + sRowOff) * sStride + c];
    dst[idx] = v;
}

// dst[r, c] = src[(c + rowOff) * sStride + r]  (zero-padded), dst is [DR x DC]
__global__ void transposeT_k(float* __restrict__ dst, const float* __restrict__ src,
                             int DR, int DC, int sR, int sC, int sStride, int rowOff)
{
    __shared__ float tbuf[32][33];
    int c0 = blockIdx.x * 32;
    int r0 = blockIdx.y * 32;
    int tx = threadIdx.x, ty = threadIdx.y;
    #pragma unroll
    for (int i = ty; i < 32; i += 8) {
        int srow = c0 + i, scol = r0 + tx;
        tbuf[i][tx] = (srow < sR && scol < sC) ? src[(size_t)(srow + rowOff) * sStride + scol] : 0.f;
    }
    __syncthreads();
    #pragma unroll
    for (int i = ty; i < 32; i += 8) {
        int r = r0 + i, c = c0 + tx;
        if (r < DR && c < DC) dst[(size_t)r * DC + c] = tbuf[tx][i];
    }
}

__global__ void tagfill_k(float* __restrict__ tg)
{
    int idx = blockIdx.x * blockDim.x + threadIdx.x;   // M_EMB * 32
    if (idx >= M_EMB * 32) return;
    int r = idx >> 5, c = idx & 31;
    int p = r & 15;
    int tt = (p < 8) ? p : 8;
    tg[(size_t)r * KT + 512 + c] = (c == tt) ? 1.f : 0.f;
}

__global__ void relations_k(const float* __restrict__ R, float* __restrict__ rel)
{
    int idx = blockIdx.x * blockDim.x + threadIdx.x;   // NBATCH * TPQ
    if (idx >= NBATCH * TPQ) return;
    int c4 = idx % TPQ;
    int b  = idx / TPQ;
    const float4* r = reinterpret_cast<const float4*>(R) + (size_t)(b * 16) * TPQ + c4;
    float4 cs = make_float4(0.f, 0.f, 0.f, 0.f);
    #pragma unroll
    for (int k = 0; k < 8; k++) {
        float4 v = r[(size_t)k * TPQ];
        cs.x += v.x; cs.y += v.y; cs.z += v.z; cs.w += v.w;
    }
    #pragma unroll
    for (int a = 0; a < 8; a++) {
        float4 v = r[(size_t)(8 + a) * TPQ];
        float4 o = make_float4(cs.x + v.x, cs.y + v.y, cs.z + v.z, cs.w + v.w);
        reinterpret_cast<float4*>(rel)[(size_t)(b * 8 + a) * TPQ + c4] = o;
    }
}

__inline__ __device__ float warp_sum(float v)
{
    #pragma unroll
    for (int o = 16; o; o >>= 1) v += __shfl_down_sync(0xffffffffu, v, o);
    return v;
}

__global__ void fout_k(const float* __restrict__ Hf, const float* __restrict__ W,
                       const float* __restrict__ bf2, float* __restrict__ fo)
{
    int row = blockIdx.x;
    const float* h = Hf + (size_t)row * TP;
    float s = 0.f;
    for (int c = threadIdx.x; c < TP; c += 128) s += h[c] * W[c];
    s = warp_sum(s);
    __shared__ float sh[4];
    if ((threadIdx.x & 31) == 0) sh[threadIdx.x >> 5] = s;
    __syncthreads();
    if (threadIdx.x == 0) fo[row] = sh[0] + sh[1] + sh[2] + sh[3] + bf2[0];
}

__global__ void loss_k(const float* __restrict__ fo, const int* __restrict__ labels,
                       float* __restrict__ out)
{
    int b = threadIdx.x;   // 512 threads
    int lab = labels[b];
    float lsum = 0.f;
    float best = -1e30f; int bi = 0;
    #pragma unroll
    for (int a = 0; a < 8; a++) {
        float f = fo[b * 8 + a];
        float l = fmaxf(f, 0.f) - f * ((a == lab) ? 1.f : 0.f) + log1pf(expf(-fabsf(f)));
        lsum += l;
        if (f > best) { best = f; bi = a; }
    }
    float cor = (bi == lab) ? 1.f : 0.f;
    lsum = warp_sum(lsum);
    cor  = warp_sum(cor);
    __shared__ float sl[16], sc[16];
    int wid = threadIdx.x >> 5, lane = threadIdx.x & 31;
    if (lane == 0) { sl[wid] = lsum; sc[wid] = cor; }
    __syncthreads();
    if (wid == 0) {
        float a = (lane < 16) ? sl[lane] : 0.f;
        float c = (lane < 16) ? sc[lane] : 0.f;
        a = warp_sum(a);
        c = warp_sum(c);
        if (lane == 0) {
            out[0] = a / (float)(NBATCH * 8);
            out[1] = c / (float)NBATCH;
        }
    }
}

// ======================= host =============================================
static inline int cdiv(int a, int b) { return (a + b - 1) / b; }

extern "C" void kernel_launch(void* const* d_in, const int* in_sizes, int n_in,
                              void* d_out, int out_size)
{
    const float* x      = (const float*)d_in[0];
    const float* W_emb  = (const float*)d_in[1];
    const float* b_emb  = (const float*)d_in[2];
    const float* Wg1    = (const float*)d_in[3];
    const float* bg1    = (const float*)d_in[4];
    const float* Wg2    = (const float*)d_in[5];
    const float* bg2    = (const float*)d_in[6];
    const float* Wg3    = (const float*)d_in[7];
    const float* bg3    = (const float*)d_in[8];
    const float* Wf1    = (const float*)d_in[9];
    const float* bf1    = (const float*)d_in[10];
    const float* Wf2    = (const float*)d_in[11];
    const float* bf2    = (const float*)d_in[12];
    const int*   labels = (const int*)d_in[13];
    float* out = (float*)d_out;

    float *tagged, *P, *Q, *H2, *R, *rel, *Hf, *fo;
    float *WembT, *W1tT, *W1bT, *W2T, *W3T, *Wf1T, *Wf2p, *b1p, *b2p, *b3p, *bf1p;
    cudaGetSymbolAddress((void**)&tagged, g_tagged);
    cudaGetSymbolAddress((void**)&P, g_P);
    cudaGetSymbolAddress((void**)&Q, g_Q);
    cudaGetSymbolAddress((void**)&H2, g_H2);
    cudaGetSymbolAddress((void**)&R, g_R);
    cudaGetSymbolAddress((void**)&rel, g_rel);
    cudaGetSymbolAddress((void**)&Hf, g_Hf);
    cudaGetSymbolAddress((void**)&fo, g_fo);
    cudaGetSymbolAddress((void**)&WembT, g_WembT);
    cudaGetSymbolAddress((void**)&W1tT, g_W1tT);
    cudaGetSymbolAddress((void**)&W1bT, g_W1bT);
    cudaGetSymbolAddress((void**)&W2T, g_W2T);
    cudaGetSymbolAddress((void**)&W3T, g_W3T);
    cudaGetSymbolAddress((void**)&Wf1T, g_Wf1T);
    cudaGetSymbolAddress((void**)&Wf2p, g_Wf2p);
    cudaGetSymbolAddress((void**)&b1p, g_b1);
    cudaGetSymbolAddress((void**)&b2p, g_b2);
    cudaGetSymbolAddress((void**)&b3p, g_b3);
    cudaGetSymbolAddress((void**)&bf1p, g_bf1);

    const int SMB = 2 * 4128 * 4;   // 33024 bytes dynamic smem
    cudaFuncSetAttribute(mmagemm_k<1,0>, cudaFuncAttributeMaxDynamicSharedMemorySize, SMB);
    cudaFuncSetAttribute(mmagemm_k<0,0>, cudaFuncAttributeMaxDynamicSharedMemorySize, SMB);
    cudaFuncSetAttribute(mmagemm_k<2,1>, cudaFuncAttributeMaxDynamicSharedMemorySize, SMB);
    cudaFuncSetAttribute(mmagemm_k<3,0>, cudaFuncAttributeMaxDynamicSharedMemorySize, SMB);
    cudaFuncSetAttribute(mmagemm_k<2,0>, cudaFuncAttributeMaxDynamicSharedMemorySize, SMB);

    dim3 tb(32, 8);
    // Transposed / padded weights: Bt[n, k] = W[k, n]
    transposeT_k<<<dim3(200, 16), tb>>>(WembT, W_emb, 512, KE, KE, 512, 512, 0);
    transposeT_k<<<dim3(17, 33), tb>>>(W1tT, Wg1, TP, KT, 521, T, T, 0);
    transposeT_k<<<dim3(17, 33), tb>>>(W1bT, Wg1, TP, KT, 521, T, T, 521);
    transposeT_k<<<dim3(33, 33), tb>>>(W2T,  Wg2, TP, TP, T, T, T, 0);
    transposeT_k<<<dim3(33, 33), tb>>>(W3T,  Wg3, TP, TP, T, T, T, 0);
    transposeT_k<<<dim3(33, 33), tb>>>(Wf1T, Wf1, TP, TP, T, T, T, 0);
    pad2d_k<<<cdiv(TP, 256), 256>>>(Wf2p, Wf2, 1, TP, 1, T, T, 0);
    pad2d_k<<<cdiv(TP, 256), 256>>>(b1p, bg1, 1, TP, 1, T, T, 0);
    pad2d_k<<<cdiv(TP, 256), 256>>>(b2p, bg2, 1, TP, 1, T, T, 0);
    pad2d_k<<<cdiv(TP, 256), 256>>>(b3p, bg3, 1, TP, 1, T, T, 0);
    pad2d_k<<<cdiv(TP, 256), 256>>>(bf1p, bf1, 1, TP, 1, T, T, 0);
    tagfill_k<<<cdiv(M_EMB * 32, 256), 256>>>(tagged);

    // emb = x @ W_emb + b_emb -> tagged[:, 0:512]  (ldc = 544)
    mmagemm_k<1,0><<<dim3(4, M_EMB/128), 256, SMB>>>(
        x, KE, nullptr, nullptr, WembT, KE, 512, tagged, KT, KE, b_emb);
    // P = tagged @ Wg1_top ; Q = tagged @ Wg1_bot
    mmagemm_k<0,0><<<dim3(9, M_EMB/128), 256, SMB>>>(
        tagged, KT, nullptr, nullptr, W1tT, KT, TP, P, TP, KT, nullptr);
    mmagemm_k<0,0><<<dim3(9, M_EMB/128), 256, SMB>>>(
        tagged, KT, nullptr, nullptr, W1bT, KT, TP, Q, TP, KT, nullptr);
    // H2 = relu(relu(P[j]+Q[k]+b1) @ Wg2 + b2)  (H1 expand fused into A producer)
    mmagemm_k<2,1><<<dim3(9, M_PAIR/128), 256, SMB>>>(
        P, TP, Q, b1p, W2T, TP, TP, H2, TP, TP, b2p);
    // R[b,k] = sum_j relu(H2 @ Wg3 + b3)  (8-row reduction fused in epilogue)
    mmagemm_k<3,0><<<dim3(9, M_PAIR/128), 256, SMB>>>(
        H2, TP, nullptr, nullptr, W3T, TP, TP, R, TP, TP, b3p);
    // relations
    relations_k<<<cdiv(NBATCH * TPQ, 256), 256>>>(R, rel);
    // Hf = relu(rel @ Wf1 + bf1)
    mmagemm_k<2,0><<<dim3(9, M_REL/128), 256, SMB>>>(
        rel, TP, nullptr, nullptr, Wf1T, TP, TP, Hf, TP, TP, bf1p);
    fout_k<<<M_REL, 128>>>(Hf, Wf2p, bf2, fo);
    loss_k<<<1, 512>>>(fo, labels, out);
}

// round 6
// speedup vs baseline: 2.1468x; 1.5161x over previous
#include <cuda_runtime.h>
#include <cuda_bf16.h>
#include <cstdint>
#include <math.h>

#define NBATCH  512
#define T       1042
#define TP      1056
#define TPQ     (TP/4)
#define KE      6400
#define KT      544
#define M_EMB   8192
#define M_PAIR  65536
#define M_REL   4096

// ---------------- scratch (device globals; no allocation) ----------------
__device__ __align__(16) float g_P[(size_t)M_EMB * TP];
__device__ __align__(16) float g_Q[(size_t)M_EMB * TP];
__device__ __align__(16) float g_R[(size_t)M_EMB * TP];
__device__ __align__(16) float g_rel[(size_t)M_REL * TP];
__device__ __align__(16) float g_Hf[(size_t)M_REL * TP];
__device__ float g_fo[M_REL];
// split (bf16 hi/lo, fragment-permuted) buffers: [tile][kb][2][1024] u32
__device__ __align__(16) uint32_t g_taggedSp[(size_t)64 * 34 * 2048];
__device__ __align__(16) uint32_t g_H1Sp[(size_t)512 * 66 * 2048];
__device__ __align__(16) uint32_t g_H2Sp[(size_t)512 * 66 * 2048];
__device__ __align__(16) uint32_t g_WembSp[(size_t)4 * 400 * 2048];
__device__ __align__(16) uint32_t g_W1tSp[(size_t)9 * 34 * 2048];
__device__ __align__(16) uint32_t g_W1bSp[(size_t)9 * 34 * 2048];
__device__ __align__(16) uint32_t g_W2Sp[(size_t)9 * 66 * 2048];
__device__ __align__(16) uint32_t g_W3Sp[(size_t)9 * 66 * 2048];
__device__ __align__(16) uint32_t g_Wf1Sp[(size_t)9 * 66 * 2048];
__device__ __align__(16) float g_Wf2p[TP];
__device__ __align__(16) float g_b1[TP];
__device__ __align__(16) float g_b2[TP];
__device__ __align__(16) float g_b3[TP];
__device__ __align__(16) float g_bf1[TP];

// ---------------- helpers -------------------------------------------------
// Split (a,b) into packed bf16x2 hi and lo words (v = hi + lo to ~bf16^2 prec).
__device__ __forceinline__ void split2(float a, float b, uint32_t& h, uint32_t& l) {
    __nv_bfloat16 ha = __float2bfloat16(a);
    __nv_bfloat16 hb = __float2bfloat16(b);
    float fa = __bfloat162float(ha), fb = __bfloat162float(hb);
    __nv_bfloat16 la = __float2bfloat16(a - fa);
    __nv_bfloat16 lb = __float2bfloat16(b - fb);
    h = (uint32_t)__bfloat16_as_ushort(ha) | ((uint32_t)__bfloat16_as_ushort(hb) << 16);
    l = (uint32_t)__bfloat16_as_ushort(la) | ((uint32_t)__bfloat16_as_ushort(lb) << 16);
}

__device__ __forceinline__ void mma16(float acc[4], const uint32_t a[4], const uint32_t b[2]) {
    asm volatile(
        "mma.sync.aligned.m16n8k16.row.col.f32.bf16.bf16.f32 "
        "{%0,%1,%2,%3},{%4,%5,%6,%7},{%8,%9},{%0,%1,%2,%3};"
        : "+f"(acc[0]), "+f"(acc[1]), "+f"(acc[2]), "+f"(acc[3])
        : "r"(a[0]), "r"(a[1]), "r"(a[2]), "r"(a[3]), "r"(b[0]), "r"(b[1]));
}

// ================= 3x-BF16 mma.sync GEMM ==================================
// C[M x N] = A[M x K] @ Bt[N x K]^T.  BM=BN=128, BK=16, 256 threads.
// Warp grid 2(m) x 4(n); warp tile 64x32; frags m16n8k16 (bf16, fp32 acc).
// acc += Ah*Bh + Ah*Bl + Al*Bh.
// B always comes pre-split+permuted from gmem (pure copy producer).
// ASRC: 0 = f32 A, split on the fly; 2 = pre-split A (pure copy).
// EPI:  0 none, 1 +bias, 2 +bias+relu, 3 +bias+relu+sum groups of 8 rows.
// AOUT: 0 = f32 C store; 1 = store C in split-fragment layout (Csp, KBC).
template<int EPI, int ASRC, int AOUT>
__global__ void __launch_bounds__(256, 1) mmagemm_k(
    const float* __restrict__ A, int lda,
    const uint32_t* __restrict__ Asp,
    const uint32_t* __restrict__ Bsp,
    int Ncols, float* __restrict__ C, int ldc,
    uint32_t* __restrict__ Csp, int KBC,
    int K, const float* __restrict__ bias)
{
    extern __shared__ uint32_t smu[];
    constexpr int A_HI = 0;
    constexpr int A_LO = 1032;
    constexpr int B_HI = 2064;
    constexpr int B_LO = 3096;
    constexpr int STG  = 4128;          // u32 per stage

    const int t  = threadIdx.x;
    const int m0 = blockIdx.y * 128, n0 = blockIdx.x * 128;
    const int KB = K >> 4;

    // ---- producer addressing (ASRC==0) ----
    const int prow = t >> 1, pks = t & 1;
    const int p8 = prow & 7, rb8 = (prow >> 3) & 1, fb = prow >> 4;
    const float* ApA = nullptr;
    if (ASRC == 0) ApA = A + (size_t)(m0 + prow) * lda + pks * 8;

    float va[8];
    uint4 hA, lA, hB, lB;

    // ---- consumer addressing ----
    const int L = t & 31, wid = t >> 5, wm = wid >> 2, wn = wid & 3;
    float acc[4][4][4];
    #pragma unroll
    for (int i = 0; i < 4; i++)
        #pragma unroll
        for (int j = 0; j < 4; j++)
            #pragma unroll
            for (int v = 0; v < 4; v++) acc[i][j][v] = 0.f;

    // ---------- fetch tile (gmem -> regs) ----------
    auto ldtile = [&](int kb) {
        const uint4* gB = (const uint4*)(Bsp + ((size_t)(blockIdx.x * KB + kb)) * 2048);
        hB = gB[t]; lB = gB[256 + t];
        if (ASRC == 2) {
            const uint4* gA = (const uint4*)(Asp + ((size_t)(blockIdx.y * KB + kb)) * 2048);
            hA = gA[t]; lA = gA[256 + t];
        } else {
            int k0 = kb * 16;
            float4 x0 = *(const float4*)(ApA + k0);
            float4 x1 = *(const float4*)(ApA + k0 + 4);
            va[0] = x0.x; va[1] = x0.y; va[2] = x0.z; va[3] = x0.w;
            va[4] = x1.x; va[5] = x1.y; va[6] = x1.z; va[7] = x1.w;
        }
    };

    // ---------- store tile (regs -> smem) ----------
    auto sttile = [&](uint32_t* stg) {
        *(uint4*)(stg + B_HI + t * 4) = hB;
        *(uint4*)(stg + B_LO + t * 4) = lB;
        if (ASRC == 2) {
            *(uint4*)(stg + A_HI + t * 4) = hA;
            *(uint4*)(stg + A_LO + t * 4) = lA;
        } else {
            #pragma unroll
            for (int j = 0; j < 4; j++) {
                uint32_t h, l;
                split2(va[2 * j], va[2 * j + 1], h, l);
                int ai = fb * 128 + (p8 * 4 + j) * 4 + rb8 + 2 * pks;
                stg[A_HI + ai] = h;
                stg[A_LO + ai] = l;
            }
        }
    };

    // ---------- consume one stage: 48 MMAs ----------
    auto consume = [&](const uint32_t* stg) {
        uint32_t ah[4][4], al[4][4], bh[4][2], bl[4][2];
        #pragma unroll
        for (int mf = 0; mf < 4; mf++) {
            const uint32_t* ab = stg + (wm * 4 + mf) * 128 + L * 4;
            *(uint4*)ah[mf] = *(const uint4*)(ab + A_HI);
            *(uint4*)al[mf] = *(const uint4*)(ab + A_LO);
        }
        #pragma unroll
        for (int nf = 0; nf < 4; nf++) {
            const uint32_t* bb = stg + (wn * 4 + nf) * 64 + L * 2;
            *(uint2*)bh[nf] = *(const uint2*)(bb + B_HI);
            *(uint2*)bl[nf] = *(const uint2*)(bb + B_LO);
        }
        #pragma unroll
        for (int mf = 0; mf < 4; mf++)
            #pragma unroll
            for (int nf = 0; nf < 4; nf++) {
                mma16(acc[mf][nf], ah[mf], bh[nf]);
                mma16(acc[mf][nf], ah[mf], bl[nf]);
                mma16(acc[mf][nf], al[mf], bh[nf]);
            }
    };

    // ---------- pipelined main loop ----------
    ldtile(0);
    sttile(smu);
    __syncthreads();
    for (int kb = 0; kb < KB; kb++) {
        if (kb + 1 < KB) ldtile(kb + 1);
        consume(smu + (kb & 1) * STG);
        if (kb + 1 < KB) sttile(smu + ((kb + 1) & 1) * STG);
        __syncthreads();
    }

    // ---------- epilogue ----------
    const int baseRow = m0 + wm * 64;
    const int colBase = n0 + wn * 32 + (L & 3) * 2;

    if (AOUT == 1) {
        const int mt = blockIdx.y;
        #pragma unroll
        for (int mf = 0; mf < 4; mf++) {
            #pragma unroll
            for (int f = 0; f < 2; f++) {
                int kbC = (n0 >> 4) + wn * 2 + f;
                if (kbC < KBC) {
                    uint32_t hi[4], lo[4];
                    #pragma unroll
                    for (int s = 0; s < 2; s++) {
                        int nf = 2 * f + s;
                        int col = colBase + nf * 8;
                        float c0 = acc[mf][nf][0], c1 = acc[mf][nf][1];
                        float c2 = acc[mf][nf][2], c3 = acc[mf][nf][3];
                        if (EPI >= 1) {
                            float2 b2 = *(const float2*)(bias + col);
                            c0 += b2.x; c1 += b2.y; c2 += b2.x; c3 += b2.y;
                        }
                        if (EPI >= 2) {
                            c0 = fmaxf(c0, 0.f); c1 = fmaxf(c1, 0.f);
                            c2 = fmaxf(c2, 0.f); c3 = fmaxf(c3, 0.f);
                        }
                        split2(c0, c1, hi[2 * s], lo[2 * s]);
                        split2(c2, c3, hi[2 * s + 1], lo[2 * s + 1]);
                    }
                    size_t base = ((size_t)mt * KBC + kbC) * 2048 + (wm * 4 + mf) * 128 + L * 4;
                    *(uint4*)(Csp + base)        = make_uint4(hi[0], hi[1], hi[2], hi[3]);
                    *(uint4*)(Csp + base + 1024) = make_uint4(lo[0], lo[1], lo[2], lo[3]);
                }
            }
        }
        return;
    }

    #pragma unroll
    for (int mf = 0; mf < 4; mf++) {
        #pragma unroll
        for (int nf = 0; nf < 4; nf++) {
            int col = colBase + nf * 8;
            bool cv = col < Ncols;
            float c0 = acc[mf][nf][0], c1 = acc[mf][nf][1];
            float c2 = acc[mf][nf][2], c3 = acc[mf][nf][3];
            if (EPI >= 1) {
                float2 b2 = cv ? *(const float2*)(bias + col) : make_float2(0.f, 0.f);
                c0 += b2.x; c1 += b2.y; c2 += b2.x; c3 += b2.y;
            }
            if (EPI >= 2) {
                c0 = fmaxf(c0, 0.f); c1 = fmaxf(c1, 0.f);
                c2 = fmaxf(c2, 0.f); c3 = fmaxf(c3, 0.f);
            }
            if (EPI == 3) {
                c0 += __shfl_down_sync(0xffffffffu, c0, 16);
                c0 += __shfl_down_sync(0xffffffffu, c0, 8);
                c0 += __shfl_down_sync(0xffffffffu, c0, 4);
                c1 += __shfl_down_sync(0xffffffffu, c1, 16);
                c1 += __shfl_down_sync(0xffffffffu, c1, 8);
                c1 += __shfl_down_sync(0xffffffffu, c1, 4);
                c2 += __shfl_down_sync(0xffffffffu, c2, 16);
                c2 += __shfl_down_sync(0xffffffffu, c2, 8);
                c2 += __shfl_down_sync(0xffffffffu, c2, 4);
                c3 += __shfl_down_sync(0xffffffffu, c3, 16);
                c3 += __shfl_down_sync(0xffffffffu, c3, 8);
                c3 += __shfl_down_sync(0xffffffffu, c3, 4);
                if (L < 4 && cv) {
                    int g = (baseRow + mf * 16) >> 3;
                    *(float2*)(C + (size_t)g * ldc + col)       = make_float2(c0, c1);
                    *(float2*)(C + (size_t)(g + 1) * ldc + col) = make_float2(c2, c3);
                }
            } else {
                if (cv) {
                    int row = baseRow + mf * 16 + (L >> 2);
                    *(float2*)(C + (size_t)row * ldc + col)       = make_float2(c0, c1);
                    *(float2*)(C + (size_t)(row + 8) * ldc + col) = make_float2(c2, c3);
                }
            }
        }
    }
}

// ============ weight transpose + split + fragment-permute =================
// Bt[n,k] = W[k+rowOff, n]; out[(nt*KB+kb)*2048 + bi] (hi), +1024 (lo).
__global__ void wsplit_k(uint32_t* __restrict__ dst, const float* __restrict__ src,
                         int NT, int KB, int sK, int sN, int sStride, int rowOff)
{
    int idx = blockIdx.x * blockDim.x + threadIdx.x;
    if (idx >= NT * KB * 1024) return;
    int bi  = idx & 1023;
    int pks = bi & 1;
    int lj  = (bi >> 1) & 31;
    int nb  = bi >> 6;
    int p8  = lj >> 2, j = lj & 3;
    int nt  = idx / (KB * 1024);
    int kb  = (idx >> 10) % KB;
    int n = nt * 128 + nb * 8 + p8;
    int k = kb * 16 + pks * 8 + 2 * j;
    float w0 = (k < sK && n < sN)     ? src[(size_t)(k + rowOff) * sStride + n]     : 0.f;
    float w1 = (k + 1 < sK && n < sN) ? src[(size_t)(k + 1 + rowOff) * sStride + n] : 0.f;
    uint32_t h, l;
    split2(w0, w1, h, l);
    size_t base = ((size_t)(idx >> 10)) * 2048 + bi;
    dst[base] = h;
    dst[base + 1024] = l;
}

// ---- tag one-hot into taggedSp kb 32..33 (cols 512..543) -----------------
__global__ void tagsplit_k(uint32_t* __restrict__ tsp)
{
    int idx = blockIdx.x * blockDim.x + threadIdx.x;   // 64 * 2 * 1024
    if (idx >= 64 * 2 * 1024) return;
    int ai = idx & 1023;
    int kb = 32 + ((idx >> 10) & 1);
    int mt = idx >> 11;
    int w = ai & 127, fbv = ai >> 7;
    int lane = w >> 2, rem = w & 3;
    int rb8 = rem & 1, pks = rem >> 1;
    int p8 = lane >> 2, j = lane & 3;
    int r = mt * 128 + fbv * 16 + rb8 * 8 + p8;
    int col = kb * 16 + pks * 8 + 2 * j;
    int tpos = ((r & 15) < 8) ? (r & 15) : 8;
    int tcol = 512 + tpos;
    uint32_t h = 0;
    if (col == tcol)     h |= 0x3F80u;          // bf16(1.0)
    if (col + 1 == tcol) h |= 0x3F80u << 16;
    size_t base = ((size_t)mt * 34 + kb) * 2048 + ai;
    tsp[base] = h;
    tsp[base + 1024] = 0u;
}

// ---- H1 expand + split: relu(P[b,j]+Q[b,k]+b1) -> H1Sp -------------------
// grid (66, 512), 256 threads; block = (kb, b).
__global__ void expandsp_k(const float* __restrict__ P, const float* __restrict__ Q,
                           const float* __restrict__ b1, uint32_t* __restrict__ H1sp)
{
    __shared__ float sP[8][16], sQ[16][16], sB[16];
    int b = blockIdx.y, kb = blockIdx.x;
    int t = threadIdx.x;
    int k0 = kb * 16;
    if (t < 96) {
        int row = t >> 2, q = t & 3;
        const float* src = (row < 8) ? (P + (size_t)(b * 16 + row) * TP)
                                     : (Q + (size_t)(b * 16 + row - 8) * TP);
        float4 v = *(const float4*)(src + k0 + q * 4);
        if (row < 8) *(float4*)&sP[row][q * 4] = v;
        else         *(float4*)&sQ[row - 8][q * 4] = v;
    } else if (t < 100) {
        int q = t - 96;
        *(float4*)&sB[q * 4] = *(const float4*)(b1 + k0 + q * 4);
    }
    __syncthreads();
    int L = t & 31;
    int p8 = L >> 2, j = L & 3;
    int fbv = t >> 5;
    uint32_t hi[4], lo[4];
    #pragma unroll
    for (int s = 0; s < 2; s++) {               // pks (k-half)
        int kA = s * 8 + 2 * j;
        #pragma unroll
        for (int rb = 0; rb < 2; rb++) {        // rb8 (row-half)
            int r = fbv * 16 + rb * 8 + p8;     // pair-row within batch (0..127)
            int jj = r & 7, kk = r >> 3;
            float e0 = fmaxf(sP[jj][kA]     + sQ[kk][kA]     + sB[kA],     0.f);
            float e1 = fmaxf(sP[jj][kA + 1] + sQ[kk][kA + 1] + sB[kA + 1], 0.f);
            split2(e0, e1, hi[2 * s + rb], lo[2 * s + rb]);
        }
    }
    size_t base = ((size_t)b * 66 + kb) * 2048 + t * 4;
    *(uint4*)(H1sp + base)        = make_uint4(hi[0], hi[1], hi[2], hi[3]);
    *(uint4*)(H1sp + base + 1024) = make_uint4(lo[0], lo[1], lo[2], lo[3]);
}

// ======================= small kernels ====================================
__global__ void pad2d_k(float* __restrict__ dst, const float* __restrict__ src,
                        int dR, int dC, int sR, int sC, int sStride, int sRowOff)
{
    int idx = blockIdx.x * blockDim.x + threadIdx.x;
    if (idx >= dR * dC) return;
    int r = idx / dC, c = idx % dC;
    float v = 0.f;
    if (r < sR && c < sC) v = src[(size_t)(r + sRowOff) * sStride + c];
    dst[idx] = v;
}

__global__ void relations_k(const float* __restrict__ R, float* __restrict__ rel)
{
    int idx = blockIdx.x * blockDim.x + threadIdx.x;   // NBATCH * TPQ
    if (idx >= NBATCH * TPQ) return;
    int c4 = idx % TPQ;
    int b  = idx / TPQ;
    const float4* r = reinterpret_cast<const float4*>(R) + (size_t)(b * 16) * TPQ + c4;
    float4 cs = make_float4(0.f, 0.f, 0.f, 0.f);
    #pragma unroll
    for (int k = 0; k < 8; k++) {
        float4 v = r[(size_t)k * TPQ];
        cs.x += v.x; cs.y += v.y; cs.z += v.z; cs.w += v.w;
    }
    #pragma unroll
    for (int a = 0; a < 8; a++) {
        float4 v = r[(size_t)(8 + a) * TPQ];
        float4 o = make_float4(cs.x + v.x, cs.y + v.y, cs.z + v.z, cs.w + v.w);
        reinterpret_cast<float4*>(rel)[(size_t)(b * 8 + a) * TPQ + c4] = o;
    }
}

__inline__ __device__ float warp_sum(float v)
{
    #pragma unroll
    for (int o = 16; o; o >>= 1) v += __shfl_down_sync(0xffffffffu, v, o);
    return v;
}

__global__ void fout_k(const float* __restrict__ Hf, const float* __restrict__ W,
                       const float* __restrict__ bf2, float* __restrict__ fo)
{
    int row = blockIdx.x;
    const float* h = Hf + (size_t)row * TP;
    float s = 0.f;
    for (int c = threadIdx.x; c < TP; c += 128) s += h[c] * W[c];
    s = warp_sum(s);
    __shared__ float sh[4];
    if ((threadIdx.x & 31) == 0) sh[threadIdx.x >> 5] = s;
    __syncthreads();
    if (threadIdx.x == 0) fo[row] = sh[0] + sh[1] + sh[2] + sh[3] + bf2[0];
}

__global__ void loss_k(const float* __restrict__ fo, const int* __restrict__ labels,
                       float* __restrict__ out)
{
    int b = threadIdx.x;   // 512 threads
    int lab = labels[b];
    float lsum = 0.f;
    float best = -1e30f; int bi = 0;
    #pragma unroll
    for (int a = 0; a < 8; a++) {
        float f = fo[b * 8 + a];
        float l = fmaxf(f, 0.f) - f * ((a == lab) ? 1.f : 0.f) + log1pf(expf(-fabsf(f)));
        lsum += l;
        if (f > best) { best = f; bi = a; }
    }
    float cor = (bi == lab) ? 1.f : 0.f;
    lsum = warp_sum(lsum);
    cor  = warp_sum(cor);
    __shared__ float sl[16], sc[16];
    int wid = threadIdx.x >> 5, lane = threadIdx.x & 31;
    if (lane == 0) { sl[wid] = lsum; sc[wid] = cor; }
    __syncthreads();
    if (wid == 0) {
        float a = (lane < 16) ? sl[lane] : 0.f;
        float c = (lane < 16) ? sc[lane] : 0.f;
        a = warp_sum(a);
        c = warp_sum(c);
        if (lane == 0) {
            out[0] = a / (float)(NBATCH * 8);
            out[1] = c / (float)NBATCH;
        }
    }
}

// ======================= host =============================================
static inline int cdiv(int a, int b) { return (a + b - 1) / b; }

extern "C" void kernel_launch(void* const* d_in, const int* in_sizes, int n_in,
                              void* d_out, int out_size)
{
    const float* x      = (const float*)d_in[0];
    const float* W_emb  = (const float*)d_in[1];
    const float* b_emb  = (const float*)d_in[2];
    const float* Wg1    = (const float*)d_in[3];
    const float* bg1    = (const float*)d_in[4];
    const float* Wg2    = (const float*)d_in[5];
    const float* bg2    = (const float*)d_in[6];
    const float* Wg3    = (const float*)d_in[7];
    const float* bg3    = (const float*)d_in[8];
    const float* Wf1    = (const float*)d_in[9];
    const float* bf1    = (const float*)d_in[10];
    const float* Wf2    = (const float*)d_in[11];
    const float* bf2    = (const float*)d_in[12];
    const int*   labels = (const int*)d_in[13];
    float* out = (float*)d_out;

    float *P, *Q, *R, *rel, *Hf, *fo;
    float *Wf2p, *b1p, *b2p, *b3p, *bf1p;
    uint32_t *taggedSp, *H1Sp, *H2Sp, *WembSp, *W1tSp, *W1bSp, *W2Sp, *W3Sp, *Wf1Sp;
    cudaGetSymbolAddress((void**)&P, g_P);
    cudaGetSymbolAddress((void**)&Q, g_Q);
    cudaGetSymbolAddress((void**)&R, g_R);
    cudaGetSymbolAddress((void**)&rel, g_rel);
    cudaGetSymbolAddress((void**)&Hf, g_Hf);
    cudaGetSymbolAddress((void**)&fo, g_fo);
    cudaGetSymbolAddress((void**)&taggedSp, g_taggedSp);
    cudaGetSymbolAddress((void**)&H1Sp, g_H1Sp);
    cudaGetSymbolAddress((void**)&H2Sp, g_H2Sp);
    cudaGetSymbolAddress((void**)&WembSp, g_WembSp);
    cudaGetSymbolAddress((void**)&W1tSp, g_W1tSp);
    cudaGetSymbolAddress((void**)&W1bSp, g_W1bSp);
    cudaGetSymbolAddress((void**)&W2Sp, g_W2Sp);
    cudaGetSymbolAddress((void**)&W3Sp, g_W3Sp);
    cudaGetSymbolAddress((void**)&Wf1Sp, g_Wf1Sp);
    cudaGetSymbolAddress((void**)&Wf2p, g_Wf2p);
    cudaGetSymbolAddress((void**)&b1p, g_b1);
    cudaGetSymbolAddress((void**)&b2p, g_b2);
    cudaGetSymbolAddress((void**)&b3p, g_b3);
    cudaGetSymbolAddress((void**)&bf1p, g_bf1);

    const int SMB = 2 * 4128 * 4;   // 33024 bytes dynamic smem
    cudaFuncSetAttribute(mmagemm_k<1,0,1>, cudaFuncAttributeMaxDynamicSharedMemorySize, SMB);
    cudaFuncSetAttribute(mmagemm_k<0,2,0>, cudaFuncAttributeMaxDynamicSharedMemorySize, SMB);
    cudaFuncSetAttribute(mmagemm_k<2,2,1>, cudaFuncAttributeMaxDynamicSharedMemorySize, SMB);
    cudaFuncSetAttribute(mmagemm_k<3,2,0>, cudaFuncAttributeMaxDynamicSharedMemorySize, SMB);
    cudaFuncSetAttribute(mmagemm_k<2,0,0>, cudaFuncAttributeMaxDynamicSharedMemorySize, SMB);

    // ---- one-time weight prep: transpose + bf16 split + fragment permute ----
    wsplit_k<<<cdiv(4 * 400 * 1024, 256), 256>>>(WembSp, W_emb, 4, 400, KE, 512, 512, 0);
    wsplit_k<<<cdiv(9 * 34 * 1024, 256), 256>>>(W1tSp, Wg1, 9, 34, 521, T, T, 0);
    wsplit_k<<<cdiv(9 * 34 * 1024, 256), 256>>>(W1bSp, Wg1, 9, 34, 521, T, T, 521);
    wsplit_k<<<cdiv(9 * 66 * 1024, 256), 256>>>(W2Sp,  Wg2, 9, 66, T, T, T, 0);
    wsplit_k<<<cdiv(9 * 66 * 1024, 256), 256>>>(W3Sp,  Wg3, 9, 66, T, T, T, 0);
    wsplit_k<<<cdiv(9 * 66 * 1024, 256), 256>>>(Wf1Sp, Wf1, 9, 66, T, T, T, 0);
    pad2d_k<<<cdiv(TP, 256), 256>>>(Wf2p, Wf2, 1, TP, 1, T, T, 0);
    pad2d_k<<<cdiv(TP, 256), 256>>>(b1p, bg1, 1, TP, 1, T, T, 0);
    pad2d_k<<<cdiv(TP, 256), 256>>>(b2p, bg2, 1, TP, 1, T, T, 0);
    pad2d_k<<<cdiv(TP, 256), 256>>>(b3p, bg3, 1, TP, 1, T, T, 0);
    pad2d_k<<<cdiv(TP, 256), 256>>>(bf1p, bf1, 1, TP, 1, T, T, 0);
    tagsplit_k<<<cdiv(64 * 2 * 1024, 256), 256>>>(taggedSp);

    // emb = x @ W_emb + b_emb -> taggedSp (split layout, kb 0..31)
    mmagemm_k<1,0,1><<<dim3(4, M_EMB / 128), 256, SMB>>>(
        x, KE, nullptr, WembSp, 512, nullptr, 0, taggedSp, 34, KE, b_emb);
    // P = tagged @ Wg1_top ; Q = tagged @ Wg1_bot  (copy-copy producers)
    mmagemm_k<0,2,0><<<dim3(9, M_EMB / 128), 256, SMB>>>(
        nullptr, 0, taggedSp, W1tSp, TP, P, TP, nullptr, 0, KT, nullptr);
    mmagemm_k<0,2,0><<<dim3(9, M_EMB / 128), 256, SMB>>>(
        nullptr, 0, taggedSp, W1bSp, TP, Q, TP, nullptr, 0, KT, nullptr);
    // H1 = relu(P[j]+Q[k]+b1), split once into H1Sp
    expandsp_k<<<dim3(66, NBATCH), 256>>>(P, Q, b1p, H1Sp);
    // H2 = relu(H1 @ Wg2 + b2) -> H2Sp (split layout)
    mmagemm_k<2,2,1><<<dim3(9, M_PAIR / 128), 256, SMB>>>(
        nullptr, 0, H1Sp, W2Sp, TP, nullptr, 0, H2Sp, 66, TP, b2p);
    // R[b,k] = sum_j relu(H2 @ Wg3 + b3)  (8-row reduction fused in epilogue)
    mmagemm_k<3,2,0><<<dim3(9, M_PAIR / 128), 256, SMB>>>(
        nullptr, 0, H2Sp, W3Sp, TP, R, TP, nullptr, 0, TP, b3p);
    // relations
    relations_k<<<cdiv(NBATCH * TPQ, 256), 256>>>(R, rel);
    // Hf = relu(rel @ Wf1 + bf1)
    mmagemm_k<2,0,0><<<dim3(9, M_REL / 128), 256, SMB>>>(
        rel, TP, nullptr, Wf1Sp, TP, Hf, TP, nullptr, 0, TP, bf1p);
    fout_k<<<M_REL, 128>>>(Hf, Wf2p, bf2, fo);
    loss_k<<<1, 512>>>(fo, labels, out);
}

// round 7
// speedup vs baseline: 2.2664x; 1.0557x over previous
#include <cuda_runtime.h>
#include <cuda_bf16.h>
#include <cstdint>
#include <math.h>

#define NBATCH  512
#define T       1042
#define TP      1056
#define TPQ     (TP/4)
#define KE      6400
#define KT      528
#define M_EMB   8192
#define M_PAIR  65536
#define M_REL   4096

// ---------------- scratch (device globals; no allocation) ----------------
__device__ __align__(16) float g_P[(size_t)M_EMB * TP];
__device__ __align__(16) float g_Q[(size_t)M_EMB * TP];
__device__ __align__(16) float g_R[(size_t)M_EMB * TP];
__device__ __align__(16) float g_rel[(size_t)M_REL * TP];
__device__ __align__(16) float g_Hf[(size_t)M_REL * TP];
__device__ float g_fo[M_REL];
// split (bf16 hi/lo, fragment-permuted) buffers: [tile][kb][2][1024] u32
__device__ __align__(16) uint32_t g_taggedSp[(size_t)64 * 33 * 2048];
__device__ __align__(16) uint32_t g_H1Sp[(size_t)512 * 66 * 2048];
__device__ __align__(16) uint32_t g_H2Sp[(size_t)512 * 66 * 2048];
__device__ __align__(16) uint32_t g_WembSp[(size_t)4 * 400 * 2048];
__device__ __align__(16) uint32_t g_W1tSp[(size_t)9 * 33 * 2048];
__device__ __align__(16) uint32_t g_W1bSp[(size_t)9 * 33 * 2048];
__device__ __align__(16) uint32_t g_W2Sp[(size_t)9 * 66 * 2048];
__device__ __align__(16) uint32_t g_W3Sp[(size_t)9 * 66 * 2048];
__device__ __align__(16) uint32_t g_Wf1Sp[(size_t)9 * 66 * 2048];
__device__ __align__(16) float g_Wf2p[TP];
__device__ __align__(16) float g_b1[TP];
__device__ __align__(16) float g_b2[TP];
__device__ __align__(16) float g_b3[TP];
__device__ __align__(16) float g_bf1[TP];

// ---------------- helpers -------------------------------------------------
__device__ __forceinline__ void split2(float a, float b, uint32_t& h, uint32_t& l) {
    __nv_bfloat16 ha = __float2bfloat16(a);
    __nv_bfloat16 hb = __float2bfloat16(b);
    float fa = __bfloat162float(ha), fb = __bfloat162float(hb);
    __nv_bfloat16 la = __float2bfloat16(a - fa);
    __nv_bfloat16 lb = __float2bfloat16(b - fb);
    h = (uint32_t)__bfloat16_as_ushort(ha) | ((uint32_t)__bfloat16_as_ushort(hb) << 16);
    l = (uint32_t)__bfloat16_as_ushort(la) | ((uint32_t)__bfloat16_as_ushort(lb) << 16);
}

__device__ __forceinline__ void mma16(float acc[4], const uint32_t a[4], const uint32_t b[2]) {
    asm volatile(
        "mma.sync.aligned.m16n8k16.row.col.f32.bf16.bf16.f32 "
        "{%0,%1,%2,%3},{%4,%5,%6,%7},{%8,%9},{%0,%1,%2,%3};"
        : "+f"(acc[0]), "+f"(acc[1]), "+f"(acc[2]), "+f"(acc[3])
        : "r"(a[0]), "r"(a[1]), "r"(a[2]), "r"(a[3]), "r"(b[0]), "r"(b[1]));
}

// ================= 3x-BF16 mma.sync GEMM ==================================
// C[M x N] = A[M x K] @ Bt[N x K]^T.  BM=128, BN=128 (NF=4) or 32 (NF=1).
// 256 threads, warp grid 2(m) x 4(n), frags m16n8k16 (bf16, fp32 acc).
// acc += Ah*Bh + Ah*Bl + Al*Bh.
// ASRC: 0 = f32 A split on the fly; 2 = pre-split A (pure copy).
// EPI:  0 none, 1 +bias, 2 +bias+relu, 3 +bias+relu+sum groups of 8 rows.
// AOUT: 0 = f32 C store; 1 = store C in split-fragment layout (Csp, KBC).
template<int EPI, int ASRC, int AOUT, int NF>
__device__ __forceinline__ void gemm_body(
    const float* __restrict__ A, int lda,
    const uint32_t* __restrict__ Asp,
    const uint32_t* __restrict__ Bsp,
    int Ncols, float* __restrict__ C, int ldc,
    uint32_t* __restrict__ Csp, int KBC,
    int K, const float* __restrict__ bias,
    uint32_t* smu)
{
    constexpr int A_HI = 0;
    constexpr int A_LO = 1032;
    constexpr int B_HI = 2064;
    constexpr int B_LO = 3096;
    constexpr int STG  = 4128;          // u32 per stage

    const int t  = threadIdx.x;
    const int m0 = blockIdx.y * 128, n0 = blockIdx.x * 128;
    const int KB = K >> 4;

    // ---- producer addressing (ASRC==0) ----
    const int prow = t >> 1, pks = t & 1;
    const int p8 = prow & 7, rb8 = (prow >> 3) & 1, fb = prow >> 4;
    const float* ApA = nullptr;
    if (ASRC == 0) ApA = A + (size_t)(m0 + prow) * lda + pks * 8;

    float va[8];
    uint4 hA, lA, hB, lB;

    // ---- consumer addressing ----
    const int L = t & 31, wid = t >> 5, wm = wid >> 2, wn = wid & 3;
    float acc[4][NF][4];
    #pragma unroll
    for (int i = 0; i < 4; i++)
        #pragma unroll
        for (int j = 0; j < NF; j++)
            #pragma unroll
            for (int v = 0; v < 4; v++) acc[i][j][v] = 0.f;

    // ---------- fetch tile (gmem -> regs) ----------
    auto ldtile = [&](int kb) {
        const uint32_t* gB = Bsp + ((size_t)(blockIdx.x * KB + kb)) * 2048;
        if (NF == 4) {
            hB = ((const uint4*)gB)[t];
            lB = ((const uint4*)gB)[256 + t];
        } else {
            hB.x = gB[t];
            lB.x = gB[1024 + t];
        }
        if (ASRC == 2) {
            const uint4* gA = (const uint4*)(Asp + ((size_t)(blockIdx.y * KB + kb)) * 2048);
            hA = gA[t]; lA = gA[256 + t];
        } else {
            int k0 = kb * 16;
            float4 x0 = *(const float4*)(ApA + k0);
            float4 x1 = *(const float4*)(ApA + k0 + 4);
            va[0] = x0.x; va[1] = x0.y; va[2] = x0.z; va[3] = x0.w;
            va[4] = x1.x; va[5] = x1.y; va[6] = x1.z; va[7] = x1.w;
        }
    };

    // ---------- store tile (regs -> smem) ----------
    auto sttile = [&](uint32_t* stg) {
        if (NF == 4) {
            *(uint4*)(stg + B_HI + t * 4) = hB;
            *(uint4*)(stg + B_LO + t * 4) = lB;
        } else {
            stg[B_HI + t] = hB.x;
            stg[B_LO + t] = lB.x;
        }
        if (ASRC == 2) {
            *(uint4*)(stg + A_HI + t * 4) = hA;
            *(uint4*)(stg + A_LO + t * 4) = lA;
        } else {
            #pragma unroll
            for (int j = 0; j < 4; j++) {
                uint32_t h, l;
                split2(va[2 * j], va[2 * j + 1], h, l);
                int ai = fb * 128 + (p8 * 4 + j) * 4 + rb8 + 2 * pks;
                stg[A_HI + ai] = h;
                stg[A_LO + ai] = l;
            }
        }
    };

    // ---------- consume one stage ----------
    auto consume = [&](const uint32_t* stg) {
        uint32_t ah[4][4], al[4][4], bh[NF][2], bl[NF][2];
        #pragma unroll
        for (int mf = 0; mf < 4; mf++) {
            const uint32_t* ab = stg + (wm * 4 + mf) * 128 + L * 4;
            *(uint4*)ah[mf] = *(const uint4*)(ab + A_HI);
            *(uint4*)al[mf] = *(const uint4*)(ab + A_LO);
        }
        #pragma unroll
        for (int nf = 0; nf < NF; nf++) {
            const uint32_t* bb = stg + (wn * NF + nf) * 64 + L * 2;
            *(uint2*)bh[nf] = *(const uint2*)(bb + B_HI);
            *(uint2*)bl[nf] = *(const uint2*)(bb + B_LO);
        }
        #pragma unroll
        for (int mf = 0; mf < 4; mf++)
            #pragma unroll
            for (int nf = 0; nf < NF; nf++) {
                mma16(acc[mf][nf], ah[mf], bh[nf]);
                mma16(acc[mf][nf], ah[mf], bl[nf]);
                mma16(acc[mf][nf], al[mf], bh[nf]);
            }
    };

    // ---------- pipelined main loop ----------
    ldtile(0);
    sttile(smu);
    __syncthreads();
    for (int kb = 0; kb < KB; kb++) {
        if (kb + 1 < KB) ldtile(kb + 1);
        consume(smu + (kb & 1) * STG);
        if (kb + 1 < KB) sttile(smu + ((kb + 1) & 1) * STG);
        __syncthreads();
    }

    // ---------- epilogue ----------
    const int baseRow = m0 + wm * 64;

    if (AOUT == 1) {
        const int mt = blockIdx.y;
        if (NF == 4) {
            #pragma unroll
            for (int mf = 0; mf < 4; mf++) {
                #pragma unroll
                for (int f = 0; f < 2; f++) {
                    int kbC = (n0 >> 4) + wn * 2 + f;
                    uint32_t hi[4], lo[4];
                    #pragma unroll
                    for (int s = 0; s < 2; s++) {
                        int nf = 2 * f + s;
                        int col = n0 + wn * 32 + nf * 8 + (L & 3) * 2;
                        float c0 = acc[mf][nf][0], c1 = acc[mf][nf][1];
                        float c2 = acc[mf][nf][2], c3 = acc[mf][nf][3];
                        if (EPI >= 1) {
                            float2 b2 = *(const float2*)(bias + col);
                            c0 += b2.x; c1 += b2.y; c2 += b2.x; c3 += b2.y;
                        }
                        if (EPI >= 2) {
                            c0 = fmaxf(c0, 0.f); c1 = fmaxf(c1, 0.f);
                            c2 = fmaxf(c2, 0.f); c3 = fmaxf(c3, 0.f);
                        }
                        split2(c0, c1, hi[2 * s], lo[2 * s]);
                        split2(c2, c3, hi[2 * s + 1], lo[2 * s + 1]);
                    }
                    size_t base = ((size_t)mt * KBC + kbC) * 2048 + (wm * 4 + mf) * 128 + L * 4;
                    *(uint4*)(Csp + base)        = make_uint4(hi[0], hi[1], hi[2], hi[3]);
                    *(uint4*)(Csp + base + 1024) = make_uint4(lo[0], lo[1], lo[2], lo[3]);
                }
            }
        } else {
            #pragma unroll
            for (int mf = 0; mf < 4; mf++) {
                int col = n0 + wn * 8 + (L & 3) * 2;
                float c0 = acc[mf][0][0], c1 = acc[mf][0][1];
                float c2 = acc[mf][0][2], c3 = acc[mf][0][3];
                if (EPI >= 1) {
                    float2 b2 = *(const float2*)(bias + col);
                    c0 += b2.x; c1 += b2.y; c2 += b2.x; c3 += b2.y;
                }
                if (EPI >= 2) {
                    c0 = fmaxf(c0, 0.f); c1 = fmaxf(c1, 0.f);
                    c2 = fmaxf(c2, 0.f); c3 = fmaxf(c3, 0.f);
                }
                uint32_t h0, l0, h1, l1;
                split2(c0, c1, h0, l0);
                split2(c2, c3, h1, l1);
                int kbC = (n0 >> 4) + (wn >> 1);
                size_t base = ((size_t)mt * KBC + kbC) * 2048 + (wm * 4 + mf) * 128
                            + L * 4 + 2 * (wn & 1);
                *(uint2*)(Csp + base)        = make_uint2(h0, h1);
                *(uint2*)(Csp + base + 1024) = make_uint2(l0, l1);
            }
        }
        return;
    }

    #pragma unroll
    for (int mf = 0; mf < 4; mf++) {
        #pragma unroll
        for (int nf = 0; nf < NF; nf++) {
            int col = n0 + wn * 8 * NF + nf * 8 + (L & 3) * 2;
            bool cv = col < Ncols;
            float c0 = acc[mf][nf][0], c1 = acc[mf][nf][1];
            float c2 = acc[mf][nf][2], c3 = acc[mf][nf][3];
            if (EPI >= 1) {
                float2 b2 = cv ? *(const float2*)(bias + col) : make_float2(0.f, 0.f);
                c0 += b2.x; c1 += b2.y; c2 += b2.x; c3 += b2.y;
            }
            if (EPI >= 2) {
                c0 = fmaxf(c0, 0.f); c1 = fmaxf(c1, 0.f);
                c2 = fmaxf(c2, 0.f); c3 = fmaxf(c3, 0.f);
            }
            if (EPI == 3) {
                c0 += __shfl_down_sync(0xffffffffu, c0, 16);
                c0 += __shfl_down_sync(0xffffffffu, c0, 8);
                c0 += __shfl_down_sync(0xffffffffu, c0, 4);
                c1 += __shfl_down_sync(0xffffffffu, c1, 16);
                c1 += __shfl_down_sync(0xffffffffu, c1, 8);
                c1 += __shfl_down_sync(0xffffffffu, c1, 4);
                c2 += __shfl_down_sync(0xffffffffu, c2, 16);
                c2 += __shfl_down_sync(0xffffffffu, c2, 8);
                c2 += __shfl_down_sync(0xffffffffu, c2, 4);
                c3 += __shfl_down_sync(0xffffffffu, c3, 16);
                c3 += __shfl_down_sync(0xffffffffu, c3, 8);
                c3 += __shfl_down_sync(0xffffffffu, c3, 4);
                if (L < 4 && cv) {
                    int g = (baseRow + mf * 16) >> 3;
                    *(float2*)(C + (size_t)g * ldc + col)       = make_float2(c0, c1);
                    *(float2*)(C + (size_t)(g + 1) * ldc + col) = make_float2(c2, c3);
                }
            } else {
                if (cv) {
                    int row = baseRow + mf * 16 + (L >> 2);
                    *(float2*)(C + (size_t)row * ldc + col)       = make_float2(c0, c1);
                    *(float2*)(C + (size_t)(row + 8) * ldc + col) = make_float2(c2, c3);
                }
            }
        }
    }
}

template<int EPI, int ASRC, int AOUT, int NARROW>
__global__ void __launch_bounds__(256, 1) mmagemm_k(
    const float* __restrict__ A, int lda,
    const uint32_t* __restrict__ Asp,
    const uint32_t* __restrict__ Bsp,
    int Ncols, float* __restrict__ C, int ldc,
    uint32_t* __restrict__ Csp, int KBC,
    int K, const float* __restrict__ bias)
{
    extern __shared__ uint32_t smu[];
    if (NARROW && blockIdx.x == gridDim.x - 1)
        gemm_body<EPI, ASRC, AOUT, 1>(A, lda, Asp, Bsp, Ncols, C, ldc, Csp, KBC, K, bias, smu);
    else
        gemm_body<EPI, ASRC, AOUT, 4>(A, lda, Asp, Bsp, Ncols, C, ldc, Csp, KBC, K, bias, smu);
}

// ============ weight transpose + split + fragment-permute =================
__global__ void wsplit_k(uint32_t* __restrict__ dst, const float* __restrict__ src,
                         int NT, int KB, int sK, int sN, int sStride, int rowOff)
{
    int idx = blockIdx.x * blockDim.x + threadIdx.x;
    if (idx >= NT * KB * 1024) return;
    int bi  = idx & 1023;
    int pks = bi & 1;
    int lj  = (bi >> 1) & 31;
    int nb  = bi >> 6;
    int p8  = lj >> 2, j = lj & 3;
    int nt  = idx / (KB * 1024);
    int kb  = (idx >> 10) % KB;
    int n = nt * 128 + nb * 8 + p8;
    int k = kb * 16 + pks * 8 + 2 * j;
    float w0 = (k < sK && n < sN)     ? src[(size_t)(k + rowOff) * sStride + n]     : 0.f;
    float w1 = (k + 1 < sK && n < sN) ? src[(size_t)(k + 1 + rowOff) * sStride + n] : 0.f;
    uint32_t h, l;
    split2(w0, w1, h, l);
    size_t base = ((size_t)(idx >> 10)) * 2048 + bi;
    dst[base] = h;
    dst[base + 1024] = l;
}

// ---- tag one-hot into taggedSp kb 32 (cols 512..527) ---------------------
__global__ void tagsplit_k(uint32_t* __restrict__ tsp)
{
    int idx = blockIdx.x * blockDim.x + threadIdx.x;   // 64 * 1024
    if (idx >= 64 * 1024) return;
    int ai = idx & 1023;
    int mt = idx >> 10;
    int w = ai & 127, fbv = ai >> 7;
    int lane = w >> 2, rem = w & 3;
    int rb8 = rem & 1, pks = rem >> 1;
    int p8 = lane >> 2, j = lane & 3;
    int r = mt * 128 + fbv * 16 + rb8 * 8 + p8;
    int col = 512 + pks * 8 + 2 * j;
    int tpos = ((r & 15) < 8) ? (r & 15) : 8;
    int tcol = 512 + tpos;
    uint32_t h = 0;
    if (col == tcol)     h |= 0x3F80u;          // bf16(1.0)
    if (col + 1 == tcol) h |= 0x3F80u << 16;
    size_t base = ((size_t)mt * 33 + 32) * 2048 + ai;
    tsp[base] = h;
    tsp[base + 1024] = 0u;
}

// ---- H1 expand + split: relu(P[b,j]+Q[b,k]+b1) -> H1Sp -------------------
__global__ void expandsp_k(const float* __restrict__ P, const float* __restrict__ Q,
                           const float* __restrict__ b1, uint32_t* __restrict__ H1sp)
{
    __shared__ float sP[8][16], sQ[16][16], sB[16];
    int b = blockIdx.y, kb = blockIdx.x;
    int t = threadIdx.x;
    int k0 = kb * 16;
    if (t < 96) {
        int row = t >> 2, q = t & 3;
        const float* src = (row < 8) ? (P + (size_t)(b * 16 + row) * TP)
                                     : (Q + (size_t)(b * 16 + row - 8) * TP);
        float4 v = *(const float4*)(src + k0 + q * 4);
        if (row < 8) *(float4*)&sP[row][q * 4] = v;
        else         *(float4*)&sQ[row - 8][q * 4] = v;
    } else if (t < 100) {
        int q = t - 96;
        *(float4*)&sB[q * 4] = *(const float4*)(b1 + k0 + q * 4);
    }
    __syncthreads();
    int L = t & 31;
    int p8 = L >> 2, j = L & 3;
    int fbv = t >> 5;
    uint32_t hi[4], lo[4];
    #pragma unroll
    for (int s = 0; s < 2; s++) {
        int kA = s * 8 + 2 * j;
        #pragma unroll
        for (int rb = 0; rb < 2; rb++) {
            int r = fbv * 16 + rb * 8 + p8;
            int jj = r & 7, kk = r >> 3;
            float e0 = fmaxf(sP[jj][kA]     + sQ[kk][kA]     + sB[kA],     0.f);
            float e1 = fmaxf(sP[jj][kA + 1] + sQ[kk][kA + 1] + sB[kA + 1], 0.f);
            split2(e0, e1, hi[2 * s + rb], lo[2 * s + rb]);
        }
    }
    size_t base = ((size_t)b * 66 + kb) * 2048 + t * 4;
    *(uint4*)(H1sp + base)        = make_uint4(hi[0], hi[1], hi[2], hi[3]);
    *(uint4*)(H1sp + base + 1024) = make_uint4(lo[0], lo[1], lo[2], lo[3]);
}

// ======================= small kernels ====================================
__global__ void pad2d_k(float* __restrict__ dst, const float* __restrict__ src,
                        int dR, int dC, int sR, int sC, int sStride, int sRowOff)
{
    int idx = blockIdx.x * blockDim.x + threadIdx.x;
    if (idx >= dR * dC) return;
    int r = idx / dC, c = idx % dC;
    float v = 0.f;
    if (r < sR && c < sC) v = src[(size_t)(r + sRowOff) * sStride + c];
    dst[idx] = v;
}

__global__ void relations_k(const float* __restrict__ R, float* __restrict__ rel)
{
    int idx = blockIdx.x * blockDim.x + threadIdx.x;   // NBATCH * TPQ
    if (idx >= NBATCH * TPQ) return;
    int c4 = idx % TPQ;
    int b  = idx / TPQ;
    const float4* r = reinterpret_cast<const float4*>(R) + (size_t)(b * 16) * TPQ + c4;
    float4 cs = make_float4(0.f, 0.f, 0.f, 0.f);
    #pragma unroll
    for (int k = 0; k < 8; k++) {
        float4 v = r[(size_t)k * TPQ];
        cs.x += v.x; cs.y += v.y; cs.z += v.z; cs.w += v.w;
    }
    #pragma unroll
    for (int a = 0; a < 8; a++) {
        float4 v = r[(size_t)(8 + a) * TPQ];
        float4 o = make_float4(cs.x + v.x, cs.y + v.y, cs.z + v.z, cs.w + v.w);
        reinterpret_cast<float4*>(rel)[(size_t)(b * 8 + a) * TPQ + c4] = o;
    }
}

__inline__ __device__ float warp_sum(float v)
{
    #pragma unroll
    for (int o = 16; o; o >>= 1) v += __shfl_down_sync(0xffffffffu, v, o);
    return v;
}

__global__ void fout_k(const float* __restrict__ Hf, const float* __restrict__ W,
                       const float* __restrict__ bf2, float* __restrict__ fo)
{
    int row = blockIdx.x;
    const float* h = Hf + (size_t)row * TP;
    float s = 0.f;
    for (int c = threadIdx.x; c < TP; c += 128) s += h[c] * W[c];
    s = warp_sum(s);
    __shared__ float sh[4];
    if ((threadIdx.x & 31) == 0) sh[threadIdx.x >> 5] = s;
    __syncthreads();
    if (threadIdx.x == 0) fo[row] = sh[0] + sh[1] + sh[2] + sh[3] + bf2[0];
}

__global__ void loss_k(const float* __restrict__ fo, const int* __restrict__ labels,
                       float* __restrict__ out)
{
    int b = threadIdx.x;   // 512 threads
    int lab = labels[b];
    float lsum = 0.f;
    float best = -1e30f; int bi = 0;
    #pragma unroll
    for (int a = 0; a < 8; a++) {
        float f = fo[b * 8 + a];
        float l = fmaxf(f, 0.f) - f * ((a == lab) ? 1.f : 0.f) + log1pf(expf(-fabsf(f)));
        lsum += l;
        if (f > best) { best = f; bi = a; }
    }
    float cor = (bi == lab) ? 1.f : 0.f;
    lsum = warp_sum(lsum);
    cor  = warp_sum(cor);
    __shared__ float sl[16], sc[16];
    int wid = threadIdx.x >> 5, lane = threadIdx.x & 31;
    if (lane == 0) { sl[wid] = lsum; sc[wid] = cor; }
    __syncthreads();
    if (wid == 0) {
        float a = (lane < 16) ? sl[lane] : 0.f;
        float c = (lane < 16) ? sc[lane] : 0.f;
        a = warp_sum(a);
        c = warp_sum(c);
        if (lane == 0) {
            out[0] = a / (float)(NBATCH * 8);
            out[1] = c / (float)NBATCH;
        }
    }
}

// ======================= host =============================================
static inline int cdiv(int a, int b) { return (a + b - 1) / b; }

extern "C" void kernel_launch(void* const* d_in, const int* in_sizes, int n_in,
                              void* d_out, int out_size)
{
    const float* x      = (const float*)d_in[0];
    const float* W_emb  = (const float*)d_in[1];
    const float* b_emb  = (const float*)d_in[2];
    const float* Wg1    = (const float*)d_in[3];
    const float* bg1    = (const float*)d_in[4];
    const float* Wg2    = (const float*)d_in[5];
    const float* bg2    = (const float*)d_in[6];
    const float* Wg3    = (const float*)d_in[7];
    const float* bg3    = (const float*)d_in[8];
    const float* Wf1    = (const float*)d_in[9];
    const float* bf1    = (const float*)d_in[10];
    const float* Wf2    = (const float*)d_in[11];
    const float* bf2    = (const float*)d_in[12];
    const int*   labels = (const int*)d_in[13];
    float* out = (float*)d_out;

    float *P, *Q, *R, *rel, *Hf, *fo;
    float *Wf2p, *b1p, *b2p, *b3p, *bf1p;
    uint32_t *taggedSp, *H1Sp, *H2Sp, *WembSp, *W1tSp, *W1bSp, *W2Sp, *W3Sp, *Wf1Sp;
    cudaGetSymbolAddress((void**)&P, g_P);
    cudaGetSymbolAddress((void**)&Q, g_Q);
    cudaGetSymbolAddress((void**)&R, g_R);
    cudaGetSymbolAddress((void**)&rel, g_rel);
    cudaGetSymbolAddress((void**)&Hf, g_Hf);
    cudaGetSymbolAddress((void**)&fo, g_fo);
    cudaGetSymbolAddress((void**)&taggedSp, g_taggedSp);
    cudaGetSymbolAddress((void**)&H1Sp, g_H1Sp);
    cudaGetSymbolAddress((void**)&H2Sp, g_H2Sp);
    cudaGetSymbolAddress((void**)&WembSp, g_WembSp);
    cudaGetSymbolAddress((void**)&W1tSp, g_W1tSp);
    cudaGetSymbolAddress((void**)&W1bSp, g_W1bSp);
    cudaGetSymbolAddress((void**)&W2Sp, g_W2Sp);
    cudaGetSymbolAddress((void**)&W3Sp, g_W3Sp);
    cudaGetSymbolAddress((void**)&Wf1Sp, g_Wf1Sp);
    cudaGetSymbolAddress((void**)&Wf2p, g_Wf2p);
    cudaGetSymbolAddress((void**)&b1p, g_b1);
    cudaGetSymbolAddress((void**)&b2p, g_b2);
    cudaGetSymbolAddress((void**)&b3p, g_b3);
    cudaGetSymbolAddress((void**)&bf1p, g_bf1);

    const int SMB = 2 * 4128 * 4;   // 33024 bytes dynamic smem
    cudaFuncSetAttribute(mmagemm_k<1,0,1,0>, cudaFuncAttributeMaxDynamicSharedMemorySize, SMB);
    cudaFuncSetAttribute(mmagemm_k<0,2,0,1>, cudaFuncAttributeMaxDynamicSharedMemorySize, SMB);
    cudaFuncSetAttribute(mmagemm_k<2,2,1,1>, cudaFuncAttributeMaxDynamicSharedMemorySize, SMB);
    cudaFuncSetAttribute(mmagemm_k<3,2,0,1>, cudaFuncAttributeMaxDynamicSharedMemorySize, SMB);
    cudaFuncSetAttribute(mmagemm_k<2,0,0,1>, cudaFuncAttributeMaxDynamicSharedMemorySize, SMB);

    // ---- one-time weight prep: transpose + bf16 split + fragment permute ----
    wsplit_k<<<cdiv(4 * 400 * 1024, 256), 256>>>(WembSp, W_emb, 4, 400, KE, 512, 512, 0);
    wsplit_k<<<cdiv(9 * 33 * 1024, 256), 256>>>(W1tSp, Wg1, 9, 33, 521, T, T, 0);
    wsplit_k<<<cdiv(9 * 33 * 1024, 256), 256>>>(W1bSp, Wg1, 9, 33, 521, T, T, 521);
    wsplit_k<<<cdiv(9 * 66 * 1024, 256), 256>>>(W2Sp,  Wg2, 9, 66, T, T, T, 0);
    wsplit_k<<<cdiv(9 * 66 * 1024, 256), 256>>>(W3Sp,  Wg3, 9, 66, T, T, T, 0);
    wsplit_k<<<cdiv(9 * 66 * 1024, 256), 256>>>(Wf1Sp, Wf1, 9, 66, T, T, T, 0);
    pad2d_k<<<cdiv(TP, 256), 256>>>(Wf2p, Wf2, 1, TP, 1, T, T, 0);
    pad2d_k<<<cdiv(TP, 256), 256>>>(b1p, bg1, 1, TP, 1, T, T, 0);
    pad2d_k<<<cdiv(TP, 256), 256>>>(b2p, bg2, 1, TP, 1, T, T, 0);
    pad2d_k<<<cdiv(TP, 256), 256>>>(b3p, bg3, 1, TP, 1, T, T, 0);
    pad2d_k<<<cdiv(TP, 256), 256>>>(bf1p, bf1, 1, TP, 1, T, T, 0);
    tagsplit_k<<<cdiv(64 * 1024, 256), 256>>>(taggedSp);

    // emb = x @ W_emb + b_emb -> taggedSp (split layout, kb 0..31; kb 32 = tags)
    mmagemm_k<1,0,1,0><<<dim3(4, M_EMB / 128), 256, SMB>>>(
        x, KE, nullptr, WembSp, 512, nullptr, 0, taggedSp, 33, KE, b_emb);
    // P = tagged @ Wg1_top ; Q = tagged @ Wg1_bot  (copy-copy; K = 528, narrow 9th tile)
    mmagemm_k<0,2,0,1><<<dim3(9, M_EMB / 128), 256, SMB>>>(
        nullptr, 0, taggedSp, W1tSp, TP, P, TP, nullptr, 0, KT, nullptr);
    mmagemm_k<0,2,0,1><<<dim3(9, M_EMB / 128), 256, SMB>>>(
        nullptr, 0, taggedSp, W1bSp, TP, Q, TP, nullptr, 0, KT, nullptr);
    // H1 = relu(P[j]+Q[k]+b1), split once into H1Sp
    expandsp_k<<<dim3(66, NBATCH), 256>>>(P, Q, b1p, H1Sp);
    // H2 = relu(H1 @ Wg2 + b2) -> H2Sp (split layout, narrow 9th tile)
    mmagemm_k<2,2,1,1><<<dim3(9, M_PAIR / 128), 256, SMB>>>(
        nullptr, 0, H1Sp, W2Sp, TP, nullptr, 0, H2Sp, 66, TP, b2p);
    // R[b,k] = sum_j relu(H2 @ Wg3 + b3)  (8-row reduction fused, narrow 9th tile)
    mmagemm_k<3,2,0,1><<<dim3(9, M_PAIR / 128), 256, SMB>>>(
        nullptr, 0, H2Sp, W3Sp, TP, R, TP, nullptr, 0, TP, b3p);
    // relations
    relations_k<<<cdiv(NBATCH * TPQ, 256), 256>>>(R, rel);
    // Hf = relu(rel @ Wf1 + bf1)  (narrow 9th tile)
    mmagemm_k<2,0,0,1><<<dim3(9, M_REL / 128), 256, SMB>>>(
        rel, TP, nullptr, Wf1Sp, TP, Hf, TP, nullptr, 0, TP, bf1p);
    fout_k<<<M_REL, 128>>>(Hf, Wf2p, bf2, fo);
    loss_k<<<1, 512>>>(fo, labels, out);
}